// round 1
// baseline (speedup 1.0000x reference)
#include <cuda_runtime.h>

#define NP     8192           // original sampled coords
#define NQ     32768          // total queries (8192 + 24576)
#define CH     64             // channels
#define SPLIT  8              // point-dimension split for K1
#define PS     (NP / SPLIT)   // 1024 points per block
#define QB     256            // queries per block / threads per block
#define NCAND  (SPLIT * 4)    // 32 merge candidates per query

// Scratch for partial top-4 per split (allocation-free rule: __device__ globals)
__device__ float g_cd[NCAND * NQ];
__device__ int   g_ci[NCAND * NQ];

// ---------------------------------------------------------------------------
// K1: per-query partial top-4 over a 1/SPLIT slice of the reference points.
// d2 replicates the reference fp32 arithmetic exactly:
//   sq = qx*qx + qy*qy            (mul, mul, add -- no contraction)
//   qc = fma(qy, cy, qx*cx)       (K=2 FMA-accumulated dot, GEMM style)
//   d2 = (sq + c2) - 2*qc         (2*qc exact => fma(-2, qc, t) bit-identical)
// Ties: scanning ascending index with strict '<' keeps the lower index,
// matching jax.lax.top_k stability.
// ---------------------------------------------------------------------------
__global__ void __launch_bounds__(QB) knn_part(
    const float2* __restrict__ coords,
    const float2* __restrict__ newc,
    const float*  __restrict__ shift)
{
    __shared__ float4 pts[PS];   // (x, y, |c|^2, pad) -- one LDS.128 per pair

    const int s    = blockIdx.y;
    const int base = s * PS;

    for (int t = threadIdx.x; t < PS; t += QB) {
        float2 p  = coords[base + t];
        float  c2 = __fadd_rn(__fmul_rn(p.x, p.x), __fmul_rn(p.y, p.y));
        pts[t] = make_float4(p.x, p.y, c2, 0.0f);
    }
    __syncthreads();

    const int i = blockIdx.x * QB + threadIdx.x;
    float2 a = (i < NP) ? coords[i] : newc[i - NP];
    const float qx = __fsub_rn(a.x, shift[0]);
    const float qy = __fsub_rn(a.y, shift[1]);
    const float sq = __fadd_rn(__fmul_rn(qx, qx), __fmul_rn(qy, qy));

    const float INF = __int_as_float(0x7f800000);
    float d0 = INF, d1 = INF, d2v = INF, d3 = INF;
    int   i0 = 0x7fffffff, i1 = 0x7fffffff, i2 = 0x7fffffff, i3 = 0x7fffffff;

    #pragma unroll 8
    for (int n = 0; n < PS; n++) {
        float4 p  = pts[n];
        float  qc = __fmaf_rn(qy, p.y, __fmul_rn(qx, p.x));
        float  t  = __fadd_rn(sq, p.z);
        float  d  = __fmaf_rn(-2.0f, qc, t);   // == (sq + c2) - 2*qc exactly
        if (d < d3) {
            const int idx = base + n;
            if (d < d2v) {
                d3 = d2v; i3 = i2;
                if (d < d1) {
                    d2v = d1; i2 = i1;
                    if (d < d0) { d1 = d0; i1 = i0; d0 = d; i0 = idx; }
                    else        { d1 = d;  i1 = idx; }
                } else { d2v = d; i2 = idx; }
            } else { d3 = d; i3 = idx; }
        }
    }

    g_cd[(s * 4 + 0) * NQ + i] = d0;  g_ci[(s * 4 + 0) * NQ + i] = i0;
    g_cd[(s * 4 + 1) * NQ + i] = d1;  g_ci[(s * 4 + 1) * NQ + i] = i1;
    g_cd[(s * 4 + 2) * NQ + i] = d2v; g_ci[(s * 4 + 2) * NQ + i] = i2;
    g_cd[(s * 4 + 3) * NQ + i] = d3;  g_ci[(s * 4 + 3) * NQ + i] = i3;
}

// ---------------------------------------------------------------------------
// K2: merge the 32 partial candidates (lexicographic (d, idx) -> global
// top-4 with jax tie-breaking), then gather values and write the mean.
// Writes are coalesced (warp lanes = consecutive queries, fixed channel);
// gathers hit the 2MB L2-resident values table.
// ---------------------------------------------------------------------------
__global__ void __launch_bounds__(QB) merge_gather(
    const float* __restrict__ values,
    float*       __restrict__ out)
{
    const int i = blockIdx.x * QB + threadIdx.x;

    const float INF = __int_as_float(0x7f800000);
    float b0 = INF, b1 = INF, b2 = INF, b3 = INF;
    int   j0 = 0x7fffffff, j1 = 0x7fffffff, j2 = 0x7fffffff, j3 = 0x7fffffff;

    #pragma unroll
    for (int c = 0; c < NCAND; c++) {
        const float d  = g_cd[c * NQ + i];
        const int   id = g_ci[c * NQ + i];
        const bool l3 = (d < b3) || (d == b3 && id < j3);
        if (l3) {
            const bool l2 = (d < b2) || (d == b2 && id < j2);
            if (l2) {
                b3 = b2; j3 = j2;
                const bool l1 = (d < b1) || (d == b1 && id < j1);
                if (l1) {
                    b2 = b1; j2 = j1;
                    const bool l0 = (d < b0) || (d == b0 && id < j0);
                    if (l0) { b1 = b0; j1 = j0; b0 = d; j0 = id; }
                    else    { b1 = d;  j1 = id; }
                } else { b2 = d; j2 = id; }
            } else { b3 = d; j3 = id; }
        }
    }

    #pragma unroll 4
    for (int c = 0; c < CH; c++) {
        const float* vr = values + c * NP;
        float v0 = __ldg(vr + j0);
        float v1 = __ldg(vr + j1);
        float v2 = __ldg(vr + j2);
        float v3 = __ldg(vr + j3);
        float sacc = __fadd_rn(__fadd_rn(__fadd_rn(v0, v1), v2), v3);
        out[c * NQ + i] = __fmul_rn(sacc, 0.25f);
    }
}

extern "C" void kernel_launch(void* const* d_in, const int* in_sizes, int n_in,
                              void* d_out, int out_size)
{
    const float*  values = (const float*)  d_in[0];  // [64, 8192]
    const float2* coords = (const float2*) d_in[1];  // [8192, 2]
    const float2* newc   = (const float2*) d_in[2];  // [24576, 2]
    const float*  shift  = (const float*)  d_in[3];  // [2]
    float* out = (float*)d_out;                      // [64, 32768]

    dim3 g1(NQ / QB, SPLIT);
    knn_part<<<g1, QB>>>(coords, newc, shift);
    merge_gather<<<NQ / QB, QB>>>(values, out);
}

// round 2
// speedup vs baseline: 2.5391x; 2.5391x over previous
#include <cuda_runtime.h>

#define NP     8192
#define NQ     32768
#define CH     64
#define G      64            // grid cells per dim
#define NCELL  (G * G)
#define HCELL  (1.0f / 64.0f)  // exact power of two
#define EPS    1e-5f         // d2 pruning margin >> fp formula error (~2e-6)

// ---- scratch (__device__ globals: allocation-free rule) ----
__device__ int    g_cnt[NCELL];
__device__ int    g_cur[NCELL];
__device__ int    g_off[NCELL + 1];
__device__ float4 g_pts[NP];     // (x, y, |c|^2, idx-as-float) cell-sorted
__device__ int4   g_nn[NQ];      // top-4 neighbor indices per query

static __device__ __forceinline__ int cell_of(float px, float py) {
    int cx = (int)(px * (float)G); if (cx > G - 1) cx = G - 1; if (cx < 0) cx = 0;
    int cy = (int)(py * (float)G); if (cy > G - 1) cy = G - 1; if (cy < 0) cy = 0;
    return cy * G + cx;
}

__global__ void k_zero() {
    int i = blockIdx.x * blockDim.x + threadIdx.x;
    if (i < NCELL) { g_cnt[i] = 0; g_cur[i] = 0; }
}

__global__ void k_hist(const float2* __restrict__ coords) {
    int i = blockIdx.x * blockDim.x + threadIdx.x;
    if (i < NP) {
        float2 p = coords[i];
        atomicAdd(&g_cnt[cell_of(p.x, p.y)], 1);
    }
}

__global__ void k_scan() {  // single block, 256 threads, 16 cells each
    __shared__ int part[256];
    int t = threadIdx.x;
    int base = t * 16;
    int loc[16];
    int sum = 0;
    #pragma unroll
    for (int k = 0; k < 16; k++) { loc[k] = sum; sum += g_cnt[base + k]; }
    part[t] = sum;
    __syncthreads();
    for (int off = 1; off < 256; off <<= 1) {
        int v = (t >= off) ? part[t - off] : 0;
        __syncthreads();
        part[t] += v;
        __syncthreads();
    }
    int pre = (t == 0) ? 0 : part[t - 1];
    #pragma unroll
    for (int k = 0; k < 16; k++) g_off[base + k] = pre + loc[k];
    if (t == 255) g_off[NCELL] = pre + sum;   // == NP
}

__global__ void k_scatter(const float2* __restrict__ coords) {
    int i = blockIdx.x * blockDim.x + threadIdx.x;
    if (i < NP) {
        float2 p = coords[i];
        int cell = cell_of(p.x, p.y);
        int pos = g_off[cell] + atomicAdd(&g_cur[cell], 1);
        float c2 = __fadd_rn(__fmul_rn(p.x, p.x), __fmul_rn(p.y, p.y));
        g_pts[pos] = make_float4(p.x, p.y, c2, __int_as_float(i));
    }
}

// ---------------------------------------------------------------------------
// Exact 4-NN via expanding grid rings. Per-pair arithmetic is bit-identical
// to the verified brute-force formula; selection is lexicographic (d, idx),
// so it is independent of visit order (scatter atomics / ring order).
// ---------------------------------------------------------------------------
__global__ void __launch_bounds__(256) k_query(
    const float2* __restrict__ coords,
    const float2* __restrict__ newc,
    const float*  __restrict__ shift)
{
    const int i = blockIdx.x * 256 + threadIdx.x;
    float2 a = (i < NP) ? coords[i] : newc[i - NP];
    const float qx = __fsub_rn(a.x, shift[0]);
    const float qy = __fsub_rn(a.y, shift[1]);
    const float sq = __fadd_rn(__fmul_rn(qx, qx), __fmul_rn(qy, qy));

    const int cx = (int)floorf(qx * (float)G);   // may be -1 near lower edge
    const int cy = (int)floorf(qy * (float)G);

    const float INF = __int_as_float(0x7f800000);
    float b0 = INF, b1 = INF, b2 = INF, b3 = INF;
    int   j0 = 0x7fffffff, j1 = 0x7fffffff, j2 = 0x7fffffff, j3 = 0x7fffffff;

    bool done = false;
    for (int r = 0; r < 96; r++) {
        if (__all_sync(0xffffffffu, done)) break;
        if (!done) {
            // ---- visit all cells at Chebyshev radius exactly r ----
            int ylo = cy - r, yhi = cy + r;
            int xlo = cx - r, xhi = cx + r;
            int iy0 = ylo < 0 ? 0 : ylo;
            int iy1 = yhi > G - 1 ? G - 1 : yhi;
            for (int iy = iy0; iy <= iy1; iy++) {
                bool yedge = (iy == ylo) || (iy == yhi);
                int ix0 = xlo < 0 ? 0 : xlo;
                int ix1 = xhi > G - 1 ? G - 1 : xhi;
                for (int ix = ix0; ix <= ix1; ix++) {
                    if (!yedge && ix != xlo && ix != xhi) continue;  // ring only
                    int cell = iy * G + ix;
                    int s = g_off[cell], e = g_off[cell + 1];
                    for (int n = s; n < e; n++) {
                        float4 p = g_pts[n];
                        float qc = __fmaf_rn(qy, p.y, __fmul_rn(qx, p.x));
                        float t  = __fadd_rn(sq, p.z);
                        float d  = __fmaf_rn(-2.0f, qc, t);
                        int  id  = __float_as_int(p.w);
                        bool l3 = (d < b3) || (d == b3 && id < j3);
                        if (l3) {
                            bool l2 = (d < b2) || (d == b2 && id < j2);
                            if (l2) {
                                b3 = b2; j3 = j2;
                                bool l1 = (d < b1) || (d == b1 && id < j1);
                                if (l1) {
                                    b2 = b1; j2 = j1;
                                    bool l0 = (d < b0) || (d == b0 && id < j0);
                                    if (l0) { b1 = b0; j1 = j0; b0 = d; j0 = id; }
                                    else    { b1 = d;  j1 = id; }
                                } else { b2 = d; j2 = id; }
                            } else { b3 = d; j3 = id; }
                        }
                    }
                }
            }
            // ---- pruning bound: min distance to any cell at radius > r ----
            float x0 = (float)(cx - r) * HCELL,     y0 = (float)(cy - r) * HCELL;
            float x1 = (float)(cx + r + 1) * HCELL, y1 = (float)(cy + r + 1) * HCELL;
            float b = fminf(fminf(qx - x0, x1 - qx), fminf(qy - y0, y1 - qy));
            if (b3 < __fmaf_rn(b, b, -EPS)) done = true;
        }
    }
    g_nn[i] = make_int4(j0, j1, j2, j3);
}

// ---------------------------------------------------------------------------
// Gather + mean, channel-split for occupancy (grid.y = 8 -> 1024 blocks)
// ---------------------------------------------------------------------------
__global__ void __launch_bounds__(256) k_gather(
    const float* __restrict__ values,
    float*       __restrict__ out)
{
    const int i  = blockIdx.x * 256 + threadIdx.x;
    const int c0 = blockIdx.y * (CH / 8);
    int4 nn = g_nn[i];
    #pragma unroll
    for (int k = 0; k < CH / 8; k++) {
        const float* vr = values + (c0 + k) * NP;
        float v0 = __ldg(vr + nn.x);
        float v1 = __ldg(vr + nn.y);
        float v2 = __ldg(vr + nn.z);
        float v3 = __ldg(vr + nn.w);
        float s = __fadd_rn(__fadd_rn(__fadd_rn(v0, v1), v2), v3);
        out[(c0 + k) * NQ + i] = __fmul_rn(s, 0.25f);
    }
}

extern "C" void kernel_launch(void* const* d_in, const int* in_sizes, int n_in,
                              void* d_out, int out_size)
{
    const float*  values = (const float*)  d_in[0];  // [64, 8192]
    const float2* coords = (const float2*) d_in[1];  // [8192, 2]
    const float2* newc   = (const float2*) d_in[2];  // [24576, 2]
    const float*  shift  = (const float*)  d_in[3];  // [2]
    float* out = (float*)d_out;                      // [64, 32768]

    k_zero   <<<NCELL / 256, 256>>>();
    k_hist   <<<NP / 256,    256>>>(coords);
    k_scan   <<<1,           256>>>();
    k_scatter<<<NP / 256,    256>>>(coords);
    k_query  <<<NQ / 256,    256>>>(coords, newc, shift);
    k_gather <<<dim3(NQ / 256, 8), 256>>>(values, out);
}

// round 3
// speedup vs baseline: 3.6829x; 1.4505x over previous
#include <cuda_runtime.h>

#define NP     8192
#define NQ     32768
#define CH     64
#define G      64
#define NCELL  (G * G)
#define HCELL  (1.0f / 64.0f)   // exact power of two
#define EPS    1e-5f            // pruning margin >> fp formula error (~2e-6)

// ---- scratch (__device__ globals: allocation-free rule) ----
__device__ int    g_cnt[NCELL],  g_cur[NCELL],  g_off[NCELL + 1];   // points
__device__ int    g_qcnt[NCELL], g_qcur[NCELL], g_qoff[NCELL + 1];  // queries
__device__ float4 g_pts[NP];     // cell-sorted points: (x, y, |c|^2, orig-id)
__device__ float4 g_q[NQ];       // cell-sorted queries: (qx, qy, |q|^2, qid)
__device__ int4   g_nn[NQ];      // per ORIGINAL qid: 4 sorted-point POSITIONS
__device__ float  g_vt[NP * CH]; // values transposed+permuted: v_t[pos][c]

static __device__ __forceinline__ int cell_clamped(float px, float py) {
    int cx = (int)(px * (float)G); cx = cx < 0 ? 0 : (cx > G - 1 ? G - 1 : cx);
    int cy = (int)(py * (float)G); cy = cy < 0 ? 0 : (cy > G - 1 ? G - 1 : cy);
    return cy * G + cx;
}

__global__ void k_zero() {
    int i = blockIdx.x * blockDim.x + threadIdx.x;
    if (i < NCELL) { g_cnt[i] = 0; g_cur[i] = 0; g_qcnt[i] = 0; g_qcur[i] = 0; }
}

__global__ void k_hist(const float2* __restrict__ coords,
                       const float2* __restrict__ newc,
                       const float*  __restrict__ shift)
{
    int i = blockIdx.x * blockDim.x + threadIdx.x;
    float sx = shift[0], sy = shift[1];
    float2 a = (i < NP) ? coords[i] : newc[i - NP];
    float qx = __fsub_rn(a.x, sx), qy = __fsub_rn(a.y, sy);
    atomicAdd(&g_qcnt[cell_clamped(qx, qy)], 1);
    if (i < NP) atomicAdd(&g_cnt[cell_clamped(a.x, a.y)], 1);
}

static __device__ __forceinline__ void scan4096(const int* __restrict__ cnt,
                                                int* __restrict__ ofs,
                                                int t, int* part, int total)
{
    int base = t * 16, loc[16], sum = 0;
    #pragma unroll
    for (int k = 0; k < 16; k++) { loc[k] = sum; sum += cnt[base + k]; }
    part[t] = sum;
    __syncthreads();
    for (int o = 1; o < 256; o <<= 1) {
        int v = (t >= o) ? part[t - o] : 0;
        __syncthreads();
        part[t] += v;
        __syncthreads();
    }
    int pre = (t == 0) ? 0 : part[t - 1];
    #pragma unroll
    for (int k = 0; k < 16; k++) ofs[base + k] = pre + loc[k];
    if (t == 255) ofs[NCELL] = total;
}

__global__ void k_scan() {
    __shared__ int part[256];
    int t = threadIdx.x;
    scan4096(g_cnt, g_off, t, part, NP);
    __syncthreads();
    scan4096(g_qcnt, g_qoff, t, part, NQ);
}

__global__ void k_scatter(const float2* __restrict__ coords,
                          const float2* __restrict__ newc,
                          const float*  __restrict__ shift)
{
    int i = blockIdx.x * blockDim.x + threadIdx.x;
    float sx = shift[0], sy = shift[1];
    float2 a = (i < NP) ? coords[i] : newc[i - NP];
    float qx = __fsub_rn(a.x, sx), qy = __fsub_rn(a.y, sy);
    float sq = __fadd_rn(__fmul_rn(qx, qx), __fmul_rn(qy, qy));
    int qc = cell_clamped(qx, qy);
    int qpos = g_qoff[qc] + atomicAdd(&g_qcur[qc], 1);
    g_q[qpos] = make_float4(qx, qy, sq, __int_as_float(i));
    if (i < NP) {
        int pc = cell_clamped(a.x, a.y);
        int pos = g_off[pc] + atomicAdd(&g_cur[pc], 1);
        float c2 = __fadd_rn(__fmul_rn(a.x, a.x), __fmul_rn(a.y, a.y));
        g_pts[pos] = make_float4(a.x, a.y, c2, __int_as_float(i));
    }
}

// values[c][orig(pos)] -> g_vt[pos][c]  (channel-contiguous, sorted order)
__global__ void k_vt(const float* __restrict__ values) {
    int idx = blockIdx.x * blockDim.x + threadIdx.x;   // NP*CH threads
    int pos = idx >> 6, c = idx & 63;
    int orig = __float_as_int(g_pts[pos].w);
    g_vt[idx] = __ldg(values + c * NP + orig);
}

// ---------------------------------------------------------------------------
// Exact 4-NN on cell-sorted queries (warp-coherent rings). Per-pair fp32
// arithmetic is identical to the verified brute-force formula; selection is
// lexicographic (d, orig_id) -> visit-order independent. Full ring rows are
// contiguous g_pts ranges (cell-major layout).
// ---------------------------------------------------------------------------
__global__ void __launch_bounds__(256) k_query()
{
    const int t = blockIdx.x * 256 + threadIdx.x;
    float4 q = g_q[t];
    const float qx = q.x, qy = q.y, sq = q.z;
    const int qid = __float_as_int(q.w);
    const int cx = (int)floorf(qx * (float)G);   // may be -1 near lower edge
    const int cy = (int)floorf(qy * (float)G);

    const float INF = __int_as_float(0x7f800000);
    float b0 = INF, b1 = INF, b2 = INF, b3 = INF;
    int   o0 = 0x7fffffff, o1 = 0x7fffffff, o2 = 0x7fffffff, o3 = 0x7fffffff;
    int   p0 = 0, p1 = 0, p2 = 0, p3 = 0;

#define PAIR(n) {                                                        \
    float4 p = g_pts[n];                                                 \
    float qc = __fmaf_rn(qy, p.y, __fmul_rn(qx, p.x));                   \
    float tt = __fadd_rn(sq, p.z);                                       \
    float d  = __fmaf_rn(-2.0f, qc, tt);                                 \
    int  id  = __float_as_int(p.w);                                      \
    if ((d < b3) || (d == b3 && id < o3)) {                              \
        if ((d < b2) || (d == b2 && id < o2)) {                          \
            b3 = b2; o3 = o2; p3 = p2;                                   \
            if ((d < b1) || (d == b1 && id < o1)) {                      \
                b2 = b1; o2 = o1; p2 = p1;                               \
                if ((d < b0) || (d == b0 && id < o0)) {                  \
                    b1 = b0; o1 = o0; p1 = p0;                           \
                    b0 = d; o0 = id; p0 = (n);                           \
                } else { b1 = d; o1 = id; p1 = (n); }                    \
            } else { b2 = d; o2 = id; p2 = (n); }                        \
        } else { b3 = d; o3 = id; p3 = (n); }                            \
    } }

    // ---- r = 0+1 merged: full 3x3 square, row-contiguous scans ----
    {
        int iy0 = cy - 1 < 0 ? 0 : cy - 1;
        int iy1 = cy + 1 > G - 1 ? G - 1 : cy + 1;
        int ix0 = cx - 1 < 0 ? 0 : cx - 1;
        int ix1 = cx + 1 > G - 1 ? G - 1 : cx + 1;
        for (int iy = iy0; iy <= iy1; iy++) {
            int s = g_off[iy * G + ix0], e = g_off[iy * G + ix1 + 1];
            for (int n = s; n < e; n++) PAIR(n)
        }
    }
    bool done;
    {
        float x0 = (float)(cx - 1) * HCELL,  y0 = (float)(cy - 1) * HCELL;
        float x1 = (float)(cx + 2) * HCELL,  y1 = (float)(cy + 2) * HCELL;
        float b = fminf(fminf(qx - x0, x1 - qx), fminf(qy - y0, y1 - qy));
        done = (b3 < __fmaf_rn(b, b, -EPS));
    }

    for (int r = 2; r < 96; r++) {
        if (__all_sync(0xffffffffu, done)) break;
        if (!done) {
            int ylo = cy - r, yhi = cy + r, xlo = cx - r, xhi = cx + r;
            int ix0 = xlo < 0 ? 0 : xlo;
            int ix1 = xhi > G - 1 ? G - 1 : xhi;
            if (ylo >= 0) {           // top row (contiguous)
                int s = g_off[ylo * G + ix0], e = g_off[ylo * G + ix1 + 1];
                for (int n = s; n < e; n++) PAIR(n)
            }
            if (yhi <= G - 1) {       // bottom row (contiguous)
                int s = g_off[yhi * G + ix0], e = g_off[yhi * G + ix1 + 1];
                for (int n = s; n < e; n++) PAIR(n)
            }
            int iy0 = ylo + 1 < 0 ? 0 : ylo + 1;
            int iy1 = yhi - 1 > G - 1 ? G - 1 : yhi - 1;
            for (int iy = iy0; iy <= iy1; iy++) {   // side columns
                if (xlo >= 0) {
                    int c = iy * G + xlo;
                    int s = g_off[c], e = g_off[c + 1];
                    for (int n = s; n < e; n++) PAIR(n)
                }
                if (xhi <= G - 1) {
                    int c = iy * G + xhi;
                    int s = g_off[c], e = g_off[c + 1];
                    for (int n = s; n < e; n++) PAIR(n)
                }
            }
            float x0 = (float)(cx - r) * HCELL,     y0 = (float)(cy - r) * HCELL;
            float x1 = (float)(cx + r + 1) * HCELL, y1 = (float)(cy + r + 1) * HCELL;
            float b = fminf(fminf(qx - x0, x1 - qx), fminf(qy - y0, y1 - qy));
            if (b3 < __fmaf_rn(b, b, -EPS)) done = true;
        }
    }
#undef PAIR
    g_nn[qid] = make_int4(p0, p1, p2, p3);   // sorted-point positions, d-order
}

// ---------------------------------------------------------------------------
// Gather from channel-contiguous v_t rows (256B per neighbor, fully used).
// Thread = original query (coalesced g_nn loads + coalesced out writes);
// channels split 16/block across grid.y.
// ---------------------------------------------------------------------------
__global__ void __launch_bounds__(256) k_gather(float* __restrict__ out)
{
    const int i  = blockIdx.x * 256 + threadIdx.x;
    const int c0 = blockIdx.y * 16;
    int4 nn = g_nn[i];
    const float4* v0 = (const float4*)(g_vt + nn.x * CH + c0);
    const float4* v1 = (const float4*)(g_vt + nn.y * CH + c0);
    const float4* v2 = (const float4*)(g_vt + nn.z * CH + c0);
    const float4* v3 = (const float4*)(g_vt + nn.w * CH + c0);
    #pragma unroll
    for (int k = 0; k < 4; k++) {
        float4 a = v0[k], b = v1[k], c = v2[k], d = v3[k];
        int cc = c0 + k * 4;
        out[(cc + 0) * NQ + i] =
            __fmul_rn(__fadd_rn(__fadd_rn(__fadd_rn(a.x, b.x), c.x), d.x), 0.25f);
        out[(cc + 1) * NQ + i] =
            __fmul_rn(__fadd_rn(__fadd_rn(__fadd_rn(a.y, b.y), c.y), d.y), 0.25f);
        out[(cc + 2) * NQ + i] =
            __fmul_rn(__fadd_rn(__fadd_rn(__fadd_rn(a.z, b.z), c.z), d.z), 0.25f);
        out[(cc + 3) * NQ + i] =
            __fmul_rn(__fadd_rn(__fadd_rn(__fadd_rn(a.w, b.w), c.w), d.w), 0.25f);
    }
}

extern "C" void kernel_launch(void* const* d_in, const int* in_sizes, int n_in,
                              void* d_out, int out_size)
{
    const float*  values = (const float*)  d_in[0];  // [64, 8192]
    const float2* coords = (const float2*) d_in[1];  // [8192, 2]
    const float2* newc   = (const float2*) d_in[2];  // [24576, 2]
    const float*  shift  = (const float*)  d_in[3];  // [2]
    float* out = (float*)d_out;                      // [64, 32768]

    k_zero   <<<NCELL / 256, 256>>>();
    k_hist   <<<NQ / 256,    256>>>(coords, newc, shift);
    k_scan   <<<1,           256>>>();
    k_scatter<<<NQ / 256,    256>>>(coords, newc, shift);
    k_vt     <<<NP * CH / 256, 256>>>(values);
    k_query  <<<NQ / 256,    256>>>();
    k_gather <<<dim3(NQ / 256, 4), 256>>>(out);
}

// round 4
// speedup vs baseline: 4.0403x; 1.0971x over previous
#include <cuda_runtime.h>

#define NP     8192
#define NQ     32768
#define CH     64
#define G      64
#define NCELL  (G * G)
#define HCELL  (1.0f / 64.0f)   // exact power of two
#define EPS    1e-5f            // pruning margin >> fp formula error (~2e-6)

#define T_TILES 512             // 32x32 transpose tiles: (64/32)*(8192/32)

// ---- scratch (__device__ globals: allocation-free rule) ----
// Counters start zero (static init) and are re-zeroed by k_gather each call.
__device__ int    g_cnt[NCELL],  g_off[NCELL + 1];    // points
__device__ int    g_qcnt[NCELL], g_qoff[NCELL + 1];   // queries
__device__ int    g_pkey[NP];    // packed cell<<16 | rank  (points)
__device__ int    g_qkey[NQ];    // packed cell<<16 | rank  (queries)
__device__ float4 g_pts[NP];     // cell-sorted points : (x, y, |c|^2, orig-id)
__device__ float4 g_q[NQ];       // cell-sorted queries: (qx, qy, |q|^2, qid)
__device__ int4   g_nn[NQ];      // per ORIGINAL qid: 4 neighbor ORIG ids
__device__ float  g_vt[NP * CH]; // values transposed: vt[orig][c]

static __device__ __forceinline__ int cell_clamped(float px, float py) {
    int cx = (int)(px * (float)G); cx = cx < 0 ? 0 : (cx > G - 1 ? G - 1 : cx);
    int cy = (int)(py * (float)G); cy = cy < 0 ? 0 : (cy > G - 1 ? G - 1 : cy);
    return cy * G + cx;
}

// ---------------------------------------------------------------------------
// K1: fused values-transpose (blocks [0, T_TILES)) + histogram-with-rank
// (blocks [T_TILES, T_TILES+128)). Counters were zeroed by the previous
// call's k_gather (or static init on the very first call).
// ---------------------------------------------------------------------------
__global__ void __launch_bounds__(256) k_pre(
    const float*  __restrict__ values,
    const float2* __restrict__ coords,
    const float2* __restrict__ newc,
    const float*  __restrict__ shift)
{
    if (blockIdx.x < T_TILES) {
        // 32x32 smem tile transpose: values[c][o] -> vt[o][c]
        __shared__ float s[32][33];
        int tc = blockIdx.x & 1;          // c-tile (2)
        int to = blockIdx.x >> 1;         // orig-tile (256)
        int tx = threadIdx.x & 31, ty = threadIdx.x >> 5;  // 32 x 8
        #pragma unroll
        for (int d = 0; d < 4; d++) {
            int cl = ty + d * 8;
            s[cl][tx] = values[(tc * 32 + cl) * NP + to * 32 + tx];
        }
        __syncthreads();
        #pragma unroll
        for (int d = 0; d < 4; d++) {
            int ol = ty + d * 8;
            g_vt[(to * 32 + ol) * CH + tc * 32 + tx] = s[tx][ol];
        }
    } else {
        int i = (blockIdx.x - T_TILES) * 256 + threadIdx.x;   // 0..NQ-1
        float sx = shift[0], sy = shift[1];
        float2 a = (i < NP) ? coords[i] : newc[i - NP];
        float qx = __fsub_rn(a.x, sx), qy = __fsub_rn(a.y, sy);
        int qc = cell_clamped(qx, qy);
        int qr = atomicAdd(&g_qcnt[qc], 1);
        g_qkey[i] = (qc << 16) | qr;
        if (i < NP) {
            int pc = cell_clamped(a.x, a.y);
            int pr = atomicAdd(&g_cnt[pc], 1);
            g_pkey[i] = (pc << 16) | pr;
        }
    }
}

// ---------------------------------------------------------------------------
// K2: dual exclusive scan of both 4096-cell histograms in one pass.
// ---------------------------------------------------------------------------
__global__ void k_scan() {
    __shared__ int pp[256], pq[256];
    int t = threadIdx.x, base = t * 16;
    int lp[16], lq[16], sp = 0, sq = 0;
    #pragma unroll
    for (int k = 0; k < 16; k++) {
        lp[k] = sp; sp += g_cnt[base + k];
        lq[k] = sq; sq += g_qcnt[base + k];
    }
    pp[t] = sp; pq[t] = sq;
    __syncthreads();
    for (int o = 1; o < 256; o <<= 1) {
        int vp = (t >= o) ? pp[t - o] : 0;
        int vq = (t >= o) ? pq[t - o] : 0;
        __syncthreads();
        pp[t] += vp; pq[t] += vq;
        __syncthreads();
    }
    int prep = (t == 0) ? 0 : pp[t - 1];
    int preq = (t == 0) ? 0 : pq[t - 1];
    #pragma unroll
    for (int k = 0; k < 16; k++) {
        g_off[base + k]  = prep + lp[k];
        g_qoff[base + k] = preq + lq[k];
    }
    if (t == 255) { g_off[NCELL] = NP; g_qoff[NCELL] = NQ; }
}

// ---------------------------------------------------------------------------
// K3: atomic-free scatter (rank was captured in k_pre).
// ---------------------------------------------------------------------------
__global__ void __launch_bounds__(256) k_scatter(
    const float2* __restrict__ coords,
    const float2* __restrict__ newc,
    const float*  __restrict__ shift)
{
    int i = blockIdx.x * 256 + threadIdx.x;
    float sx = shift[0], sy = shift[1];
    float2 a = (i < NP) ? coords[i] : newc[i - NP];
    float qx = __fsub_rn(a.x, sx), qy = __fsub_rn(a.y, sy);
    float sq = __fadd_rn(__fmul_rn(qx, qx), __fmul_rn(qy, qy));
    int qk = g_qkey[i];
    g_q[g_qoff[qk >> 16] + (qk & 0xffff)] =
        make_float4(qx, qy, sq, __int_as_float(i));
    if (i < NP) {
        int pk = g_pkey[i];
        float c2 = __fadd_rn(__fmul_rn(a.x, a.x), __fmul_rn(a.y, a.y));
        g_pts[g_off[pk >> 16] + (pk & 0xffff)] =
            make_float4(a.x, a.y, c2, __int_as_float(i));
    }
}

// ---------------------------------------------------------------------------
// K4: exact 4-NN via expanding rings on cell-sorted queries. Per-pair fp32
// arithmetic identical to the verified brute force; selection lexicographic
// (d, orig_id) -> visit-order independent. Ring rows are contiguous ranges.
// ---------------------------------------------------------------------------
__global__ void __launch_bounds__(256) k_query()
{
    const int t = blockIdx.x * 256 + threadIdx.x;
    float4 q = g_q[t];
    const float qx = q.x, qy = q.y, sq = q.z;
    const int qid = __float_as_int(q.w);
    const int cx = (int)floorf(qx * (float)G);   // may be -1 near lower edge
    const int cy = (int)floorf(qy * (float)G);

    const float INF = __int_as_float(0x7f800000);
    float b0 = INF, b1 = INF, b2 = INF, b3 = INF;
    int   o0 = 0x7fffffff, o1 = 0x7fffffff, o2 = 0x7fffffff, o3 = 0x7fffffff;

#define PAIR(n) {                                                        \
    float4 p = g_pts[n];                                                 \
    float qc = __fmaf_rn(qy, p.y, __fmul_rn(qx, p.x));                   \
    float tt = __fadd_rn(sq, p.z);                                       \
    float d  = __fmaf_rn(-2.0f, qc, tt);                                 \
    int  id  = __float_as_int(p.w);                                      \
    if ((d < b3) || (d == b3 && id < o3)) {                              \
        if ((d < b2) || (d == b2 && id < o2)) {                          \
            b3 = b2; o3 = o2;                                            \
            if ((d < b1) || (d == b1 && id < o1)) {                      \
                b2 = b1; o2 = o1;                                        \
                if ((d < b0) || (d == b0 && id < o0)) {                  \
                    b1 = b0; o1 = o0; b0 = d; o0 = id;                   \
                } else { b1 = d; o1 = id; }                              \
            } else { b2 = d; o2 = id; }                                  \
        } else { b3 = d; o3 = id; }                                      \
    } }

    // ---- r = 0+1 merged: full 3x3 square, row-contiguous scans ----
    {
        int iy0 = cy - 1 < 0 ? 0 : cy - 1;
        int iy1 = cy + 1 > G - 1 ? G - 1 : cy + 1;
        int ix0 = cx - 1 < 0 ? 0 : cx - 1;
        int ix1 = cx + 1 > G - 1 ? G - 1 : cx + 1;
        for (int iy = iy0; iy <= iy1; iy++) {
            int s = g_off[iy * G + ix0], e = g_off[iy * G + ix1 + 1];
            for (int n = s; n < e; n++) PAIR(n)
        }
    }
    bool done;
    {
        float x0 = (float)(cx - 1) * HCELL,  y0 = (float)(cy - 1) * HCELL;
        float x1 = (float)(cx + 2) * HCELL,  y1 = (float)(cy + 2) * HCELL;
        float b = fminf(fminf(qx - x0, x1 - qx), fminf(qy - y0, y1 - qy));
        done = (b3 < __fmaf_rn(b, b, -EPS));
    }

    for (int r = 2; r < 96; r++) {
        if (__all_sync(0xffffffffu, done)) break;
        if (!done) {
            int ylo = cy - r, yhi = cy + r, xlo = cx - r, xhi = cx + r;
            int ix0 = xlo < 0 ? 0 : xlo;
            int ix1 = xhi > G - 1 ? G - 1 : xhi;
            if (ylo >= 0) {
                int s = g_off[ylo * G + ix0], e = g_off[ylo * G + ix1 + 1];
                for (int n = s; n < e; n++) PAIR(n)
            }
            if (yhi <= G - 1) {
                int s = g_off[yhi * G + ix0], e = g_off[yhi * G + ix1 + 1];
                for (int n = s; n < e; n++) PAIR(n)
            }
            int iy0 = ylo + 1 < 0 ? 0 : ylo + 1;
            int iy1 = yhi - 1 > G - 1 ? G - 1 : yhi - 1;
            for (int iy = iy0; iy <= iy1; iy++) {
                if (xlo >= 0) {
                    int c = iy * G + xlo;
                    int s = g_off[c], e = g_off[c + 1];
                    for (int n = s; n < e; n++) PAIR(n)
                }
                if (xhi <= G - 1) {
                    int c = iy * G + xhi;
                    int s = g_off[c], e = g_off[c + 1];
                    for (int n = s; n < e; n++) PAIR(n)
                }
            }
            float x0 = (float)(cx - r) * HCELL,     y0 = (float)(cy - r) * HCELL;
            float x1 = (float)(cx + r + 1) * HCELL, y1 = (float)(cy + r + 1) * HCELL;
            float b = fminf(fminf(qx - x0, x1 - qx), fminf(qy - y0, y1 - qy));
            if (b3 < __fmaf_rn(b, b, -EPS)) done = true;
        }
    }
#undef PAIR
    g_nn[qid] = make_int4(o0, o1, o2, o3);   // ORIG ids, distance order
}

// ---------------------------------------------------------------------------
// K5: gather from channel-contiguous vt rows (orig-id indexed) + mean.
// Also re-zeroes the histogram counters for the next graph replay.
// ---------------------------------------------------------------------------
__global__ void __launch_bounds__(256) k_gather(float* __restrict__ out)
{
    const int i  = blockIdx.x * 256 + threadIdx.x;
    if (blockIdx.y == 0 && i < NCELL) { g_cnt[i] = 0; g_qcnt[i] = 0; }

    const int c0 = blockIdx.y * 16;
    int4 nn = g_nn[i];
    const float4* v0 = (const float4*)(g_vt + nn.x * CH + c0);
    const float4* v1 = (const float4*)(g_vt + nn.y * CH + c0);
    const float4* v2 = (const float4*)(g_vt + nn.z * CH + c0);
    const float4* v3 = (const float4*)(g_vt + nn.w * CH + c0);
    #pragma unroll
    for (int k = 0; k < 4; k++) {
        float4 a = v0[k], b = v1[k], c = v2[k], d = v3[k];
        int cc = c0 + k * 4;
        out[(cc + 0) * NQ + i] =
            __fmul_rn(__fadd_rn(__fadd_rn(__fadd_rn(a.x, b.x), c.x), d.x), 0.25f);
        out[(cc + 1) * NQ + i] =
            __fmul_rn(__fadd_rn(__fadd_rn(__fadd_rn(a.y, b.y), c.y), d.y), 0.25f);
        out[(cc + 2) * NQ + i] =
            __fmul_rn(__fadd_rn(__fadd_rn(__fadd_rn(a.z, b.z), c.z), d.z), 0.25f);
        out[(cc + 3) * NQ + i] =
            __fmul_rn(__fadd_rn(__fadd_rn(__fadd_rn(a.w, b.w), c.w), d.w), 0.25f);
    }
}

extern "C" void kernel_launch(void* const* d_in, const int* in_sizes, int n_in,
                              void* d_out, int out_size)
{
    const float*  values = (const float*)  d_in[0];  // [64, 8192]
    const float2* coords = (const float2*) d_in[1];  // [8192, 2]
    const float2* newc   = (const float2*) d_in[2];  // [24576, 2]
    const float*  shift  = (const float*)  d_in[3];  // [2]
    float* out = (float*)d_out;                      // [64, 32768]

    k_pre    <<<T_TILES + NQ / 256, 256>>>(values, coords, newc, shift);
    k_scan   <<<1, 256>>>();
    k_scatter<<<NQ / 256, 256>>>(coords, newc, shift);
    k_query  <<<NQ / 256, 256>>>();
    k_gather <<<dim3(NQ / 256, 4), 256>>>(out);
}

// round 5
// speedup vs baseline: 4.8018x; 1.1885x over previous
#include <cuda_runtime.h>

#define NP     8192
#define NQ     32768
#define CH     64
#define G      64
#define NCELL  (G * G)
#define HCELL  (1.0f / 64.0f)   // exact power of two
#define EPS    1e-5f            // pruning margin >> fp formula error (~2e-6)

#define T_TILES 512             // 32x32 transpose tiles: (64/32)*(8192/32)
#define L      4                // lanes cooperating per query

// ---- scratch (__device__ globals: allocation-free rule) ----
// Counters start zero (static init) and are re-zeroed by k_gather each call.
__device__ int    g_cnt[NCELL],  g_off[NCELL + 1];    // points
__device__ int    g_qcnt[NCELL], g_qoff[NCELL + 1];   // queries
__device__ int    g_pkey[NP];    // packed cell<<16 | rank  (points)
__device__ int    g_qkey[NQ];    // packed cell<<16 | rank  (queries)
__device__ float4 g_pts[NP];     // cell-sorted points : (x, y, |c|^2, orig-id)
__device__ float4 g_q[NQ];       // cell-sorted queries: (qx, qy, |q|^2, qid)
__device__ int4   g_nn[NQ];      // per ORIGINAL qid: 4 neighbor ORIG ids
__device__ float  g_vt[NP * CH]; // values transposed: vt[orig][c]

static __device__ __forceinline__ int cell_clamped(float px, float py) {
    int cx = (int)(px * (float)G); cx = cx < 0 ? 0 : (cx > G - 1 ? G - 1 : cx);
    int cy = (int)(py * (float)G); cy = cy < 0 ? 0 : (cy > G - 1 ? G - 1 : cy);
    return cy * G + cx;
}

// ---------------------------------------------------------------------------
// K1: fused values-transpose (blocks [0, T_TILES)) + histogram-with-rank.
// ---------------------------------------------------------------------------
__global__ void __launch_bounds__(256) k_pre(
    const float*  __restrict__ values,
    const float2* __restrict__ coords,
    const float2* __restrict__ newc,
    const float*  __restrict__ shift)
{
    if (blockIdx.x < T_TILES) {
        __shared__ float s[32][33];
        int tc = blockIdx.x & 1;
        int to = blockIdx.x >> 1;
        int tx = threadIdx.x & 31, ty = threadIdx.x >> 5;
        #pragma unroll
        for (int d = 0; d < 4; d++) {
            int cl = ty + d * 8;
            s[cl][tx] = values[(tc * 32 + cl) * NP + to * 32 + tx];
        }
        __syncthreads();
        #pragma unroll
        for (int d = 0; d < 4; d++) {
            int ol = ty + d * 8;
            g_vt[(to * 32 + ol) * CH + tc * 32 + tx] = s[tx][ol];
        }
    } else {
        int i = (blockIdx.x - T_TILES) * 256 + threadIdx.x;   // 0..NQ-1
        float sx = shift[0], sy = shift[1];
        float2 a = (i < NP) ? coords[i] : newc[i - NP];
        float qx = __fsub_rn(a.x, sx), qy = __fsub_rn(a.y, sy);
        int qc = cell_clamped(qx, qy);
        int qr = atomicAdd(&g_qcnt[qc], 1);
        g_qkey[i] = (qc << 16) | qr;
        if (i < NP) {
            int pc = cell_clamped(a.x, a.y);
            int pr = atomicAdd(&g_cnt[pc], 1);
            g_pkey[i] = (pc << 16) | pr;
        }
    }
}

// ---------------------------------------------------------------------------
// K2: dual exclusive scan of both 4096-cell histograms in one pass.
// ---------------------------------------------------------------------------
__global__ void k_scan() {
    __shared__ int pp[256], pq[256];
    int t = threadIdx.x, base = t * 16;
    int lp[16], lq[16], sp = 0, sq = 0;
    #pragma unroll
    for (int k = 0; k < 16; k++) {
        lp[k] = sp; sp += g_cnt[base + k];
        lq[k] = sq; sq += g_qcnt[base + k];
    }
    pp[t] = sp; pq[t] = sq;
    __syncthreads();
    for (int o = 1; o < 256; o <<= 1) {
        int vp = (t >= o) ? pp[t - o] : 0;
        int vq = (t >= o) ? pq[t - o] : 0;
        __syncthreads();
        pp[t] += vp; pq[t] += vq;
        __syncthreads();
    }
    int prep = (t == 0) ? 0 : pp[t - 1];
    int preq = (t == 0) ? 0 : pq[t - 1];
    #pragma unroll
    for (int k = 0; k < 16; k++) {
        g_off[base + k]  = prep + lp[k];
        g_qoff[base + k] = preq + lq[k];
    }
    if (t == 255) { g_off[NCELL] = NP; g_qoff[NCELL] = NQ; }
}

// ---------------------------------------------------------------------------
// K3: atomic-free scatter (rank captured in k_pre).
// ---------------------------------------------------------------------------
__global__ void __launch_bounds__(256) k_scatter(
    const float2* __restrict__ coords,
    const float2* __restrict__ newc,
    const float*  __restrict__ shift)
{
    int i = blockIdx.x * 256 + threadIdx.x;
    float sx = shift[0], sy = shift[1];
    float2 a = (i < NP) ? coords[i] : newc[i - NP];
    float qx = __fsub_rn(a.x, sx), qy = __fsub_rn(a.y, sy);
    float sq = __fadd_rn(__fmul_rn(qx, qx), __fmul_rn(qy, qy));
    int qk = g_qkey[i];
    g_q[g_qoff[qk >> 16] + (qk & 0xffff)] =
        make_float4(qx, qy, sq, __int_as_float(i));
    if (i < NP) {
        int pk = g_pkey[i];
        float c2 = __fadd_rn(__fmul_rn(a.x, a.x), __fmul_rn(a.y, a.y));
        g_pts[g_off[pk >> 16] + (pk & 0xffff)] =
            make_float4(a.x, a.y, c2, __int_as_float(i));
    }
}

// ---------------------------------------------------------------------------
// K4: exact 4-NN, 4 lanes per query. Lanes stride-split each contiguous
// point run, keep private lexicographic top-4s, merge via a sorted-list
// shuffle tournament. Termination bound uses ub = min_lane(b3) >= true b3,
// so pruning is conservative-safe. Per-pair fp32 arithmetic identical to
// the verified brute force; ids unique -> merge/selection order-exact.
// ---------------------------------------------------------------------------
__global__ void __launch_bounds__(256) k_query()
{
    const int gt   = blockIdx.x * 256 + threadIdx.x;
    const int grp  = gt >> 2;          // query index (sorted order)
    const int lane = gt & 3;

    float4 q = g_q[grp];
    const float qx = q.x, qy = q.y, sq = q.z;
    const int qid = __float_as_int(q.w);
    const int cx = (int)floorf(qx * (float)G);   // may be -1 near lower edge
    const int cy = (int)floorf(qy * (float)G);

    const float INF = __int_as_float(0x7f800000);
    float b0 = INF, b1 = INF, b2 = INF, b3 = INF;
    int   o0 = 0x7fffffff, o1 = 0x7fffffff, o2 = 0x7fffffff, o3 = 0x7fffffff;

#define PAIR(n) {                                                        \
    float4 p = g_pts[n];                                                 \
    float qc = __fmaf_rn(qy, p.y, __fmul_rn(qx, p.x));                   \
    float tt = __fadd_rn(sq, p.z);                                       \
    float d  = __fmaf_rn(-2.0f, qc, tt);                                 \
    int  id  = __float_as_int(p.w);                                      \
    if ((d < b3) || (d == b3 && id < o3)) {                              \
        if ((d < b2) || (d == b2 && id < o2)) {                          \
            b3 = b2; o3 = o2;                                            \
            if ((d < b1) || (d == b1 && id < o1)) {                      \
                b2 = b1; o2 = o1;                                        \
                if ((d < b0) || (d == b0 && id < o0)) {                  \
                    b1 = b0; o1 = o0; b0 = d; o0 = id;                   \
                } else { b1 = d; o1 = id; }                              \
            } else { b2 = d; o2 = id; }                                  \
        } else { b3 = d; o3 = id; }                                      \
    } }

#define RUN(s_, e_) { for (int n = (s_) + lane; n < (e_); n += L) PAIR(n) }

    // ---- r = 0+1 merged: full 3x3 square, row-contiguous scans ----
    {
        int iy0 = cy - 1 < 0 ? 0 : cy - 1;
        int iy1 = cy + 1 > G - 1 ? G - 1 : cy + 1;
        int ix0 = cx - 1 < 0 ? 0 : cx - 1;
        int ix1 = cx + 1 > G - 1 ? G - 1 : cx + 1;
        for (int iy = iy0; iy <= iy1; iy++)
            RUN(g_off[iy * G + ix0], g_off[iy * G + ix1 + 1])
    }
    // group-wide conservative 4th-best upper bound: min over lanes of b3
    float ub = b3;
    ub = fminf(ub, __shfl_xor_sync(0xffffffffu, ub, 1, 4));
    ub = fminf(ub, __shfl_xor_sync(0xffffffffu, ub, 2, 4));
    bool done;
    {
        float x0 = (float)(cx - 1) * HCELL,  y0 = (float)(cy - 1) * HCELL;
        float x1 = (float)(cx + 2) * HCELL,  y1 = (float)(cy + 2) * HCELL;
        float b = fminf(fminf(qx - x0, x1 - qx), fminf(qy - y0, y1 - qy));
        done = (ub < __fmaf_rn(b, b, -EPS));
    }

    for (int r = 2; r < 96; r++) {
        if (__all_sync(0xffffffffu, done)) break;
        if (!done) {
            int ylo = cy - r, yhi = cy + r, xlo = cx - r, xhi = cx + r;
            int ix0 = xlo < 0 ? 0 : xlo;
            int ix1 = xhi > G - 1 ? G - 1 : xhi;
            if (ylo >= 0)
                RUN(g_off[ylo * G + ix0], g_off[ylo * G + ix1 + 1])
            if (yhi <= G - 1)
                RUN(g_off[yhi * G + ix0], g_off[yhi * G + ix1 + 1])
            int iy0 = ylo + 1 < 0 ? 0 : ylo + 1;
            int iy1 = yhi - 1 > G - 1 ? G - 1 : yhi - 1;
            for (int iy = iy0; iy <= iy1; iy++) {
                if (xlo >= 0) {
                    int c = iy * G + xlo;
                    RUN(g_off[c], g_off[c + 1])
                }
                if (xhi <= G - 1) {
                    int c = iy * G + xhi;
                    RUN(g_off[c], g_off[c + 1])
                }
            }
        }
        // bound must be re-evaluated group-uniformly (shfl needs all 4 lanes)
        float nub = b3;
        nub = fminf(nub, __shfl_xor_sync(0xffffffffu, nub, 1, 4));
        nub = fminf(nub, __shfl_xor_sync(0xffffffffu, nub, 2, 4));
        if (!done) {
            float x0 = (float)(cx - r) * HCELL,     y0 = (float)(cy - r) * HCELL;
            float x1 = (float)(cx + r + 1) * HCELL, y1 = (float)(cy + r + 1) * HCELL;
            float b = fminf(fminf(qx - x0, x1 - qx), fminf(qy - y0, y1 - qy));
            if (nub < __fmaf_rn(b, b, -EPS)) done = true;
        }
    }
#undef RUN
#undef PAIR

    // ---- merge 4 sorted lane lists -> global top-4 (shuffle tournament) ----
    int res0, res1, res2, res3;
    int h = 0;
    #pragma unroll
    for (int k = 0; k < 4; k++) {
        float cd = (h == 0) ? b0 : (h == 1) ? b1 : (h == 2) ? b2
                 : (h == 3) ? b3 : INF;
        int   ci = (h == 0) ? o0 : (h == 1) ? o1 : (h == 2) ? o2
                 : (h == 3) ? o3 : 0x7fffffff;
        float md = cd; int mi = ci;
        #pragma unroll
        for (int s = 1; s < 4; s <<= 1) {
            float od = __shfl_xor_sync(0xffffffffu, md, s, 4);
            int   oi = __shfl_xor_sync(0xffffffffu, mi, s, 4);
            if (od < md || (od == md && oi < mi)) { md = od; mi = oi; }
        }
        if (k == 0) res0 = mi; else if (k == 1) res1 = mi;
        else if (k == 2) res2 = mi; else res3 = mi;
        if (cd == md && ci == mi) h++;   // exactly one lane advances (ids unique)
    }
    if (lane == 0) g_nn[qid] = make_int4(res0, res1, res2, res3);
}

// ---------------------------------------------------------------------------
// K5: gather from channel-contiguous vt rows + mean; re-zero counters.
// ---------------------------------------------------------------------------
__global__ void __launch_bounds__(256) k_gather(float* __restrict__ out)
{
    const int i  = blockIdx.x * 256 + threadIdx.x;
    if (blockIdx.y == 0 && i < NCELL) { g_cnt[i] = 0; g_qcnt[i] = 0; }

    const int c0 = blockIdx.y * 16;
    int4 nn = g_nn[i];
    const float4* v0 = (const float4*)(g_vt + nn.x * CH + c0);
    const float4* v1 = (const float4*)(g_vt + nn.y * CH + c0);
    const float4* v2 = (const float4*)(g_vt + nn.z * CH + c0);
    const float4* v3 = (const float4*)(g_vt + nn.w * CH + c0);
    #pragma unroll
    for (int k = 0; k < 4; k++) {
        float4 a = v0[k], b = v1[k], c = v2[k], d = v3[k];
        int cc = c0 + k * 4;
        out[(cc + 0) * NQ + i] =
            __fmul_rn(__fadd_rn(__fadd_rn(__fadd_rn(a.x, b.x), c.x), d.x), 0.25f);
        out[(cc + 1) * NQ + i] =
            __fmul_rn(__fadd_rn(__fadd_rn(__fadd_rn(a.y, b.y), c.y), d.y), 0.25f);
        out[(cc + 2) * NQ + i] =
            __fmul_rn(__fadd_rn(__fadd_rn(__fadd_rn(a.z, b.z), c.z), d.z), 0.25f);
        out[(cc + 3) * NQ + i] =
            __fmul_rn(__fadd_rn(__fadd_rn(__fadd_rn(a.w, b.w), c.w), d.w), 0.25f);
    }
}

extern "C" void kernel_launch(void* const* d_in, const int* in_sizes, int n_in,
                              void* d_out, int out_size)
{
    const float*  values = (const float*)  d_in[0];  // [64, 8192]
    const float2* coords = (const float2*) d_in[1];  // [8192, 2]
    const float2* newc   = (const float2*) d_in[2];  // [24576, 2]
    const float*  shift  = (const float*)  d_in[3];  // [2]
    float* out = (float*)d_out;                      // [64, 32768]

    k_pre    <<<T_TILES + NQ / 256, 256>>>(values, coords, newc, shift);
    k_scan   <<<1, 256>>>();
    k_scatter<<<NQ / 256, 256>>>(coords, newc, shift);
    k_query  <<<NQ * L / 256, 256>>>();
    k_gather <<<dim3(NQ / 256, 4), 256>>>(out);
}

// round 6
// speedup vs baseline: 5.0306x; 1.0477x over previous
#include <cuda_runtime.h>

#define NP     8192
#define NQ     32768
#define CH     64
#define G      64
#define NCELL  (G * G)
#define HCELL  (1.0f / 64.0f)   // exact power of two
#define EPS    1e-5f            // pruning margin >> fp formula error (~2e-6)

#define T_TILES 512             // 32x32 transpose tiles: (64/32)*(8192/32)
#define L      8                // lanes cooperating per query

// ---- scratch (__device__ globals: allocation-free rule) ----
// Counters start zero (static init) and are re-zeroed by k_gather each call.
__device__ int    g_cnt[NCELL],  g_off[NCELL + 1];    // points
__device__ int    g_qcnt[NCELL], g_qoff[NCELL + 1];   // queries
__device__ int    g_pkey[NP];    // packed cell<<16 | rank  (points)
__device__ int    g_qkey[NQ];    // packed cell<<16 | rank  (queries)
__device__ float4 g_pts[NP];     // cell-sorted points : (x, y, |c|^2, orig-id)
__device__ float4 g_q[NQ];       // cell-sorted queries: (qx, qy, |q|^2, qid)
__device__ int4   g_nn[NQ];      // per ORIGINAL qid: 4 neighbor ORIG ids
__device__ float  g_vt[NP * CH]; // values transposed: vt[orig][c]

static __device__ __forceinline__ int cell_clamped(float px, float py) {
    int cx = (int)(px * (float)G); cx = cx < 0 ? 0 : (cx > G - 1 ? G - 1 : cx);
    int cy = (int)(py * (float)G); cy = cy < 0 ? 0 : (cy > G - 1 ? G - 1 : cy);
    return cy * G + cx;
}

// ---------------------------------------------------------------------------
// K1: fused values-transpose (blocks [0, T_TILES)) + histogram-with-rank.
// ---------------------------------------------------------------------------
__global__ void __launch_bounds__(256) k_pre(
    const float*  __restrict__ values,
    const float2* __restrict__ coords,
    const float2* __restrict__ newc,
    const float*  __restrict__ shift)
{
    if (blockIdx.x < T_TILES) {
        __shared__ float s[32][33];
        int tc = blockIdx.x & 1;
        int to = blockIdx.x >> 1;
        int tx = threadIdx.x & 31, ty = threadIdx.x >> 5;
        #pragma unroll
        for (int d = 0; d < 4; d++) {
            int cl = ty + d * 8;
            s[cl][tx] = values[(tc * 32 + cl) * NP + to * 32 + tx];
        }
        __syncthreads();
        #pragma unroll
        for (int d = 0; d < 4; d++) {
            int ol = ty + d * 8;
            g_vt[(to * 32 + ol) * CH + tc * 32 + tx] = s[tx][ol];
        }
    } else {
        int i = (blockIdx.x - T_TILES) * 256 + threadIdx.x;   // 0..NQ-1
        float sx = shift[0], sy = shift[1];
        float2 a = (i < NP) ? coords[i] : newc[i - NP];
        float qx = __fsub_rn(a.x, sx), qy = __fsub_rn(a.y, sy);
        int qc = cell_clamped(qx, qy);
        int qr = atomicAdd(&g_qcnt[qc], 1);
        g_qkey[i] = (qc << 16) | qr;
        if (i < NP) {
            int pc = cell_clamped(a.x, a.y);
            int pr = atomicAdd(&g_cnt[pc], 1);
            g_pkey[i] = (pc << 16) | pr;
        }
    }
}

// ---------------------------------------------------------------------------
// K2: dual exclusive scan of both 4096-cell histograms in one pass.
// ---------------------------------------------------------------------------
__global__ void k_scan() {
    __shared__ int pp[256], pq[256];
    int t = threadIdx.x, base = t * 16;
    int lp[16], lq[16], sp = 0, sq = 0;
    #pragma unroll
    for (int k = 0; k < 16; k++) {
        lp[k] = sp; sp += g_cnt[base + k];
        lq[k] = sq; sq += g_qcnt[base + k];
    }
    pp[t] = sp; pq[t] = sq;
    __syncthreads();
    for (int o = 1; o < 256; o <<= 1) {
        int vp = (t >= o) ? pp[t - o] : 0;
        int vq = (t >= o) ? pq[t - o] : 0;
        __syncthreads();
        pp[t] += vp; pq[t] += vq;
        __syncthreads();
    }
    int prep = (t == 0) ? 0 : pp[t - 1];
    int preq = (t == 0) ? 0 : pq[t - 1];
    #pragma unroll
    for (int k = 0; k < 16; k++) {
        g_off[base + k]  = prep + lp[k];
        g_qoff[base + k] = preq + lq[k];
    }
    if (t == 255) { g_off[NCELL] = NP; g_qoff[NCELL] = NQ; }
}

// ---------------------------------------------------------------------------
// K3: atomic-free scatter (rank captured in k_pre).
// ---------------------------------------------------------------------------
__global__ void __launch_bounds__(256) k_scatter(
    const float2* __restrict__ coords,
    const float2* __restrict__ newc,
    const float*  __restrict__ shift)
{
    int i = blockIdx.x * 256 + threadIdx.x;
    float sx = shift[0], sy = shift[1];
    float2 a = (i < NP) ? coords[i] : newc[i - NP];
    float qx = __fsub_rn(a.x, sx), qy = __fsub_rn(a.y, sy);
    float sq = __fadd_rn(__fmul_rn(qx, qx), __fmul_rn(qy, qy));
    int qk = g_qkey[i];
    g_q[g_qoff[qk >> 16] + (qk & 0xffff)] =
        make_float4(qx, qy, sq, __int_as_float(i));
    if (i < NP) {
        int pk = g_pkey[i];
        float c2 = __fadd_rn(__fmul_rn(a.x, a.x), __fmul_rn(a.y, a.y));
        g_pts[g_off[pk >> 16] + (pk & 0xffff)] =
            make_float4(a.x, a.y, c2, __int_as_float(i));
    }
}

// ---------------------------------------------------------------------------
// K4: exact 4-NN, 8 lanes per query. One uniform 5x5 (r<=2) sweep over
// contiguous row-runs, then a tournament merge giving the TRUE group b3
// for the pruning bound (passes with prob ~1-1e-7). Rare sparse groups
// continue with conservative rings and re-merge. Per-pair fp32 arithmetic
// identical to the verified brute force; (d, orig_id) selection exact.
// ---------------------------------------------------------------------------
__global__ void __launch_bounds__(256) k_query()
{
    const int gt   = blockIdx.x * 256 + threadIdx.x;
    const int grp  = gt >> 3;          // query index (sorted order)
    const int lane = gt & 7;

    float4 q = g_q[grp];
    const float qx = q.x, qy = q.y, sq = q.z;
    const int qid = __float_as_int(q.w);
    const int cx = (int)floorf(qx * (float)G);   // may be -1 near lower edge
    const int cy = (int)floorf(qy * (float)G);

    const float INF = __int_as_float(0x7f800000);
    float b0 = INF, b1 = INF, b2 = INF, b3 = INF;
    int   o0 = 0x7fffffff, o1 = 0x7fffffff, o2 = 0x7fffffff, o3 = 0x7fffffff;

#define PAIR(n) {                                                        \
    float4 p = g_pts[n];                                                 \
    float qc = __fmaf_rn(qy, p.y, __fmul_rn(qx, p.x));                   \
    float tt = __fadd_rn(sq, p.z);                                       \
    float d  = __fmaf_rn(-2.0f, qc, tt);                                 \
    int  id  = __float_as_int(p.w);                                      \
    if ((d < b3) || (d == b3 && id < o3)) {                              \
        if ((d < b2) || (d == b2 && id < o2)) {                          \
            b3 = b2; o3 = o2;                                            \
            if ((d < b1) || (d == b1 && id < o1)) {                      \
                b2 = b1; o2 = o1;                                        \
                if ((d < b0) || (d == b0 && id < o0)) {                  \
                    b1 = b0; o1 = o0; b0 = d; o0 = id;                   \
                } else { b1 = d; o1 = id; }                              \
            } else { b2 = d; o2 = id; }                                  \
        } else { b3 = d; o3 = id; }                                      \
    } }

#define RUN(s_, e_) { for (int n = (s_) + lane; n < (e_); n += L) PAIR(n) }

// Tournament merge of 8 sorted lane lists -> group top-4 (ids + 4th dist).
// All lanes compute identical winners. Heads advance on exact (d,id) match;
// real candidates always precede INF padding within a lane list.
#define MERGE(R0, R1, R2, R3, B3V) {                                    \
    int h = 0;                                                          \
    _Pragma("unroll")                                                   \
    for (int k = 0; k < 4; k++) {                                       \
        float cd = (h == 0) ? b0 : (h == 1) ? b1 : (h == 2) ? b2        \
                 : (h == 3) ? b3 : INF;                                 \
        int   ci = (h == 0) ? o0 : (h == 1) ? o1 : (h == 2) ? o2        \
                 : (h == 3) ? o3 : 0x7fffffff;                          \
        float md = cd; int mi = ci;                                     \
        _Pragma("unroll")                                               \
        for (int s = 1; s < L; s <<= 1) {                               \
            float od = __shfl_xor_sync(0xffffffffu, md, s, L);          \
            int   oi = __shfl_xor_sync(0xffffffffu, mi, s, L);          \
            if (od < md || (od == md && oi < mi)) { md = od; mi = oi; } \
        }                                                               \
        if (k == 0) R0 = mi; else if (k == 1) R1 = mi;                  \
        else if (k == 2) R2 = mi; else { R3 = mi; B3V = md; }           \
        if (cd == md && ci == mi) h++;                                  \
    } }

    // ---- uniform 5x5 sweep (r = 0..2 merged, row-contiguous) ----
    {
        int iy0 = cy - 2 < 0 ? 0 : cy - 2;
        int iy1 = cy + 2 > G - 1 ? G - 1 : cy + 2;
        int ix0 = cx - 2 < 0 ? 0 : cx - 2;
        int ix1 = cx + 2 > G - 1 ? G - 1 : cx + 2;
        for (int iy = iy0; iy <= iy1; iy++)
            RUN(g_off[iy * G + ix0], g_off[iy * G + ix1 + 1])
    }

    // ---- merge now: true group b3 drives the pruning bound ----
    int res0, res1, res2, res3;
    float mb3;
    MERGE(res0, res1, res2, res3, mb3)

    bool done;
    {
        float x0 = (float)(cx - 2) * HCELL,  y0 = (float)(cy - 2) * HCELL;
        float x1 = (float)(cx + 3) * HCELL,  y1 = (float)(cy + 3) * HCELL;
        float b = fminf(fminf(qx - x0, x1 - qx), fminf(qy - y0, y1 - qy));
        done = (mb3 < __fmaf_rn(b, b, -EPS));
    }
    const bool early = done;

    if (!__all_sync(0xffffffffu, done)) {
        // ---- rare safety net: expanding rings from r=3 ----
        for (int r = 3; r < 96; r++) {
            if (__all_sync(0xffffffffu, done)) break;
            if (!done) {
                int ylo = cy - r, yhi = cy + r, xlo = cx - r, xhi = cx + r;
                int ix0 = xlo < 0 ? 0 : xlo;
                int ix1 = xhi > G - 1 ? G - 1 : xhi;
                if (ylo >= 0)
                    RUN(g_off[ylo * G + ix0], g_off[ylo * G + ix1 + 1])
                if (yhi <= G - 1)
                    RUN(g_off[yhi * G + ix0], g_off[yhi * G + ix1 + 1])
                int iy0 = ylo + 1 < 0 ? 0 : ylo + 1;
                int iy1 = yhi - 1 > G - 1 ? G - 1 : yhi - 1;
                for (int iy = iy0; iy <= iy1; iy++) {
                    if (xlo >= 0) {
                        int c = iy * G + xlo;
                        RUN(g_off[c], g_off[c + 1])
                    }
                    if (xhi <= G - 1) {
                        int c = iy * G + xhi;
                        RUN(g_off[c], g_off[c + 1])
                    }
                }
            }
            // conservative group bound: min over lanes of lane-local b3
            float nub = b3;
            nub = fminf(nub, __shfl_xor_sync(0xffffffffu, nub, 1, L));
            nub = fminf(nub, __shfl_xor_sync(0xffffffffu, nub, 2, L));
            nub = fminf(nub, __shfl_xor_sync(0xffffffffu, nub, 4, L));
            if (!done) {
                float x0 = (float)(cx - r) * HCELL,     y0 = (float)(cy - r) * HCELL;
                float x1 = (float)(cx + r + 1) * HCELL, y1 = (float)(cy + r + 1) * HCELL;
                float b = fminf(fminf(qx - x0, x1 - qx), fminf(qy - y0, y1 - qy));
                if (nub < __fmaf_rn(b, b, -EPS)) done = true;
            }
        }
        if (!early) MERGE(res0, res1, res2, res3, mb3)   // re-merge updated lists
    }
#undef MERGE
#undef RUN
#undef PAIR
    if (lane == 0) g_nn[qid] = make_int4(res0, res1, res2, res3);
}

// ---------------------------------------------------------------------------
// K5: gather from channel-contiguous vt rows + mean; re-zero counters.
// ---------------------------------------------------------------------------
__global__ void __launch_bounds__(256) k_gather(float* __restrict__ out)
{
    const int i  = blockIdx.x * 256 + threadIdx.x;
    if (blockIdx.y == 0 && i < NCELL) { g_cnt[i] = 0; g_qcnt[i] = 0; }

    const int c0 = blockIdx.y * 16;
    int4 nn = g_nn[i];
    const float4* v0 = (const float4*)(g_vt + nn.x * CH + c0);
    const float4* v1 = (const float4*)(g_vt + nn.y * CH + c0);
    const float4* v2 = (const float4*)(g_vt + nn.z * CH + c0);
    const float4* v3 = (const float4*)(g_vt + nn.w * CH + c0);
    #pragma unroll
    for (int k = 0; k < 4; k++) {
        float4 a = v0[k], b = v1[k], c = v2[k], d = v3[k];
        int cc = c0 + k * 4;
        out[(cc + 0) * NQ + i] =
            __fmul_rn(__fadd_rn(__fadd_rn(__fadd_rn(a.x, b.x), c.x), d.x), 0.25f);
        out[(cc + 1) * NQ + i] =
            __fmul_rn(__fadd_rn(__fadd_rn(__fadd_rn(a.y, b.y), c.y), d.y), 0.25f);
        out[(cc + 2) * NQ + i] =
            __fmul_rn(__fadd_rn(__fadd_rn(__fadd_rn(a.z, b.z), c.z), d.z), 0.25f);
        out[(cc + 3) * NQ + i] =
            __fmul_rn(__fadd_rn(__fadd_rn(__fadd_rn(a.w, b.w), c.w), d.w), 0.25f);
    }
}

extern "C" void kernel_launch(void* const* d_in, const int* in_sizes, int n_in,
                              void* d_out, int out_size)
{
    const float*  values = (const float*)  d_in[0];  // [64, 8192]
    const float2* coords = (const float2*) d_in[1];  // [8192, 2]
    const float2* newc   = (const float2*) d_in[2];  // [24576, 2]
    const float*  shift  = (const float*)  d_in[3];  // [2]
    float* out = (float*)d_out;                      // [64, 32768]

    k_pre    <<<T_TILES + NQ / 256, 256>>>(values, coords, newc, shift);
    k_scan   <<<1, 256>>>();
    k_scatter<<<NQ / 256, 256>>>(coords, newc, shift);
    k_query  <<<NQ * L / 256, 256>>>();
    k_gather <<<dim3(NQ / 256, 4), 256>>>(out);
}

// round 7
// speedup vs baseline: 5.2079x; 1.0352x over previous
#include <cuda_runtime.h>

#define NP     8192
#define NQ     32768
#define CH     64
#define G      64
#define NCELL  (G * G)
#define HCELL  (1.0f / 64.0f)   // exact power of two
#define EPS    1e-5f            // pruning margin >> fp formula error (~2e-6)

#define T_TILES 512             // 32x32 transpose tiles: (64/32)*(8192/32)
#define L      8                // lanes cooperating per query
#define HB     (NQ / 256)       // hist blocks in k_pre

// ---- scratch (__device__ globals: allocation-free rule) ----
// Counters start zero (static init) and are re-zeroed by k_gather each call.
__device__ int    g_cnt[NCELL],  g_off[NCELL + 1];    // points
__device__ int    g_qcnt[NCELL], g_qoff[NCELL + 1];   // queries
__device__ unsigned g_done;      // k_pre tail-block counter (self-resetting)
__device__ int    g_pkey[NP];    // packed cell<<16 | rank  (points)
__device__ int    g_qkey[NQ];    // packed cell<<16 | rank  (queries)
__device__ float4 g_pts[NP];     // cell-sorted points : (x, y, |c|^2, orig-id)
__device__ float4 g_q[NQ];       // cell-sorted queries: (qx, qy, |q|^2, qid)
__device__ int4   g_nn[NQ];      // per ORIGINAL qid: 4 neighbor ORIG ids
__device__ float  g_vt[NP * CH]; // values transposed: vt[orig][c]

static __device__ __forceinline__ int cell_clamped(float px, float py) {
    int cx = (int)(px * (float)G); cx = cx < 0 ? 0 : (cx > G - 1 ? G - 1 : cx);
    int cy = (int)(py * (float)G); cy = cy < 0 ? 0 : (cy > G - 1 ? G - 1 : cy);
    return cy * G + cx;
}

// ---------------------------------------------------------------------------
// K1: histogram-with-rank; LAST block to finish also runs the dual scan
// (threadfence + done-counter tail-block pattern, counter self-resets).
// ---------------------------------------------------------------------------
__global__ void __launch_bounds__(256) k_pre(
    const float2* __restrict__ coords,
    const float2* __restrict__ newc,
    const float*  __restrict__ shift)
{
    int i = blockIdx.x * 256 + threadIdx.x;   // 0..NQ-1
    float sx = shift[0], sy = shift[1];
    float2 a = (i < NP) ? coords[i] : newc[i - NP];
    float qx = __fsub_rn(a.x, sx), qy = __fsub_rn(a.y, sy);
    int qc = cell_clamped(qx, qy);
    int qr = atomicAdd(&g_qcnt[qc], 1);
    g_qkey[i] = (qc << 16) | qr;
    if (i < NP) {
        int pc = cell_clamped(a.x, a.y);
        int pr = atomicAdd(&g_cnt[pc], 1);
        g_pkey[i] = (pc << 16) | pr;
    }

    __threadfence();
    __shared__ bool isLast;
    if (threadIdx.x == 0)
        isLast = (atomicAdd(&g_done, 1u) == HB - 1);
    __syncthreads();
    if (!isLast) return;
    if (threadIdx.x == 0) g_done = 0;          // reset for next replay

    // ---- dual exclusive scan of both 4096-cell histograms ----
    __shared__ int pp[256], pq[256];
    int t = threadIdx.x, base = t * 16;
    int lp[16], lq[16], sp = 0, sq = 0;
    #pragma unroll
    for (int k = 0; k < 16; k++) {
        lp[k] = sp; sp += g_cnt[base + k];
        lq[k] = sq; sq += g_qcnt[base + k];
    }
    pp[t] = sp; pq[t] = sq;
    __syncthreads();
    for (int o = 1; o < 256; o <<= 1) {
        int vp = (t >= o) ? pp[t - o] : 0;
        int vq = (t >= o) ? pq[t - o] : 0;
        __syncthreads();
        pp[t] += vp; pq[t] += vq;
        __syncthreads();
    }
    int prep = (t == 0) ? 0 : pp[t - 1];
    int preq = (t == 0) ? 0 : pq[t - 1];
    #pragma unroll
    for (int k = 0; k < 16; k++) {
        g_off[base + k]  = prep + lp[k];
        g_qoff[base + k] = preq + lq[k];
    }
    if (t == 255) { g_off[NCELL] = NP; g_qoff[NCELL] = NQ; }
}

// ---------------------------------------------------------------------------
// K2: atomic-free scatter (blocks [0,HB)) + values-transpose (rest).
// Transpose is independent work riding along to overlap the DRAM read.
// ---------------------------------------------------------------------------
__global__ void __launch_bounds__(256) k_scatter(
    const float*  __restrict__ values,
    const float2* __restrict__ coords,
    const float2* __restrict__ newc,
    const float*  __restrict__ shift)
{
    if (blockIdx.x >= HB) {
        __shared__ float s[32][33];
        int tb = blockIdx.x - HB;
        int tc = tb & 1;
        int to = tb >> 1;
        int tx = threadIdx.x & 31, ty = threadIdx.x >> 5;
        #pragma unroll
        for (int d = 0; d < 4; d++) {
            int cl = ty + d * 8;
            s[cl][tx] = values[(tc * 32 + cl) * NP + to * 32 + tx];
        }
        __syncthreads();
        #pragma unroll
        for (int d = 0; d < 4; d++) {
            int ol = ty + d * 8;
            g_vt[(to * 32 + ol) * CH + tc * 32 + tx] = s[tx][ol];
        }
        return;
    }
    int i = blockIdx.x * 256 + threadIdx.x;
    float sx = shift[0], sy = shift[1];
    float2 a = (i < NP) ? coords[i] : newc[i - NP];
    float qx = __fsub_rn(a.x, sx), qy = __fsub_rn(a.y, sy);
    float sq = __fadd_rn(__fmul_rn(qx, qx), __fmul_rn(qy, qy));
    int qk = g_qkey[i];
    g_q[g_qoff[qk >> 16] + (qk & 0xffff)] =
        make_float4(qx, qy, sq, __int_as_float(i));
    if (i < NP) {
        int pk = g_pkey[i];
        float c2 = __fadd_rn(__fmul_rn(a.x, a.x), __fmul_rn(a.y, a.y));
        g_pts[g_off[pk >> 16] + (pk & 0xffff)] =
            make_float4(a.x, a.y, c2, __int_as_float(i));
    }
}

// ---------------------------------------------------------------------------
// K3: exact 4-NN, 8 lanes/query, ADAPTIVE sweep:
//   3x3 sweep -> merge (true group b3) -> r=1 box bound   (~95% stop here)
//   ring-2 sweep (guarded per group) -> re-merge -> r=2 box bound
//   safety rings r>=3 (conservative lane-local bound) -> final merge.
// Groups already done participating in re-merges is harmless: points beyond
// a passed bound satisfy d >= bound^2 - 2e-6 > group b3, so they can never
// displace a true top-4 element from any lane list. Per-pair fp32 arithmetic
// identical to the verified brute force; (d, orig_id) selection exact.
// ---------------------------------------------------------------------------
__global__ void __launch_bounds__(256) k_query()
{
    const int gt   = blockIdx.x * 256 + threadIdx.x;
    const int grp  = gt >> 3;          // query index (sorted order)
    const int lane = gt & 7;

    float4 q = g_q[grp];
    const float qx = q.x, qy = q.y, sq = q.z;
    const int qid = __float_as_int(q.w);
    const int cx = (int)floorf(qx * (float)G);   // may be -1 near lower edge
    const int cy = (int)floorf(qy * (float)G);

    const float INF = __int_as_float(0x7f800000);
    float b0 = INF, b1 = INF, b2 = INF, b3 = INF;
    int   o0 = 0x7fffffff, o1 = 0x7fffffff, o2 = 0x7fffffff, o3 = 0x7fffffff;

#define PAIR(n) {                                                        \
    float4 p = g_pts[n];                                                 \
    float qc = __fmaf_rn(qy, p.y, __fmul_rn(qx, p.x));                   \
    float tt = __fadd_rn(sq, p.z);                                       \
    float d  = __fmaf_rn(-2.0f, qc, tt);                                 \
    int  id  = __float_as_int(p.w);                                      \
    if ((d < b3) || (d == b3 && id < o3)) {                              \
        if ((d < b2) || (d == b2 && id < o2)) {                          \
            b3 = b2; o3 = o2;                                            \
            if ((d < b1) || (d == b1 && id < o1)) {                      \
                b2 = b1; o2 = o1;                                        \
                if ((d < b0) || (d == b0 && id < o0)) {                  \
                    b1 = b0; o1 = o0; b0 = d; o0 = id;                   \
                } else { b1 = d; o1 = id; }                              \
            } else { b2 = d; o2 = id; }                                  \
        } else { b3 = d; o3 = id; }                                      \
    } }

#define RUN(s_, e_) { for (int n = (s_) + lane; n < (e_); n += L) PAIR(n) }

#define MERGE(R0, R1, R2, R3, B3V) {                                    \
    int h = 0;                                                          \
    _Pragma("unroll")                                                   \
    for (int k = 0; k < 4; k++) {                                       \
        float cd = (h == 0) ? b0 : (h == 1) ? b1 : (h == 2) ? b2        \
                 : (h == 3) ? b3 : INF;                                 \
        int   ci = (h == 0) ? o0 : (h == 1) ? o1 : (h == 2) ? o2        \
                 : (h == 3) ? o3 : 0x7fffffff;                          \
        float md = cd; int mi = ci;                                     \
        _Pragma("unroll")                                               \
        for (int s = 1; s < L; s <<= 1) {                               \
            float od = __shfl_xor_sync(0xffffffffu, md, s, L);          \
            int   oi = __shfl_xor_sync(0xffffffffu, mi, s, L);          \
            if (od < md || (od == md && oi < mi)) { md = od; mi = oi; } \
        }                                                               \
        if (k == 0) R0 = mi; else if (k == 1) R1 = mi;                  \
        else if (k == 2) R2 = mi; else { R3 = mi; B3V = md; }           \
        if (cd == md && ci == mi) h++;                                  \
    } }

// min distance from q to the edge of the box [(cx-e)H,(cx+e+1)H] x (same in y)
#define BOXBOUND(e_, bv_) {                                              \
    float x0 = (float)(cx - (e_)) * HCELL, y0 = (float)(cy - (e_)) * HCELL; \
    float x1 = (float)(cx + (e_) + 1) * HCELL, y1 = (float)(cy + (e_) + 1) * HCELL; \
    bv_ = fminf(fminf(qx - x0, x1 - qx), fminf(qy - y0, y1 - qy)); }

    // ---- phase 1: 3x3 sweep (row-contiguous) ----
    {
        int iy0 = cy - 1 < 0 ? 0 : cy - 1;
        int iy1 = cy + 1 > G - 1 ? G - 1 : cy + 1;
        int ix0 = cx - 1 < 0 ? 0 : cx - 1;
        int ix1 = cx + 1 > G - 1 ? G - 1 : cx + 1;
        for (int iy = iy0; iy <= iy1; iy++)
            RUN(g_off[iy * G + ix0], g_off[iy * G + ix1 + 1])
    }
    int res0, res1, res2, res3;
    float mb3;
    MERGE(res0, res1, res2, res3, mb3)

    float bb; BOXBOUND(1, bb)
    bool done = (mb3 < __fmaf_rn(bb, bb, -EPS));

    if (!__all_sync(0xffffffffu, done)) {
        // ---- phase 2: ring r=2 (guarded per group; no shfl inside) ----
        if (!done) {
            int ix0 = cx - 2 < 0 ? 0 : cx - 2;
            int ix1 = cx + 2 > G - 1 ? G - 1 : cx + 2;
            if (cy - 2 >= 0)
                RUN(g_off[(cy - 2) * G + ix0], g_off[(cy - 2) * G + ix1 + 1])
            if (cy + 2 <= G - 1)
                RUN(g_off[(cy + 2) * G + ix0], g_off[(cy + 2) * G + ix1 + 1])
            int iy0 = cy - 1 < 0 ? 0 : cy - 1;
            int iy1 = cy + 1 > G - 1 ? G - 1 : cy + 1;
            for (int iy = iy0; iy <= iy1; iy++) {
                if (cx - 2 >= 0) {
                    int c = iy * G + cx - 2;
                    RUN(g_off[c], g_off[c + 1])
                }
                if (cx + 2 <= G - 1) {
                    int c = iy * G + cx + 2;
                    RUN(g_off[c], g_off[c + 1])
                }
            }
        }
        MERGE(res0, res1, res2, res3, mb3)   // uniform re-merge (safe for done)
        BOXBOUND(2, bb)
        done = done || (mb3 < __fmaf_rn(bb, bb, -EPS));

        if (!__all_sync(0xffffffffu, done)) {
            // ---- phase 3: safety rings r>=3 ----
            for (int r = 3; r < 96; r++) {
                if (__all_sync(0xffffffffu, done)) break;
                if (!done) {
                    int ylo = cy - r, yhi = cy + r, xlo = cx - r, xhi = cx + r;
                    int ix0 = xlo < 0 ? 0 : xlo;
                    int ix1 = xhi > G - 1 ? G - 1 : xhi;
                    if (ylo >= 0)
                        RUN(g_off[ylo * G + ix0], g_off[ylo * G + ix1 + 1])
                    if (yhi <= G - 1)
                        RUN(g_off[yhi * G + ix0], g_off[yhi * G + ix1 + 1])
                    int iy0 = ylo + 1 < 0 ? 0 : ylo + 1;
                    int iy1 = yhi - 1 > G - 1 ? G - 1 : yhi - 1;
                    for (int iy = iy0; iy <= iy1; iy++) {
                        if (xlo >= 0) {
                            int c = iy * G + xlo;
                            RUN(g_off[c], g_off[c + 1])
                        }
                        if (xhi <= G - 1) {
                            int c = iy * G + xhi;
                            RUN(g_off[c], g_off[c + 1])
                        }
                    }
                }
                float nub = b3;   // conservative: min over lanes of lane b3
                nub = fminf(nub, __shfl_xor_sync(0xffffffffu, nub, 1, L));
                nub = fminf(nub, __shfl_xor_sync(0xffffffffu, nub, 2, L));
                nub = fminf(nub, __shfl_xor_sync(0xffffffffu, nub, 4, L));
                if (!done) {
                    float b2v; BOXBOUND(r, b2v)
                    if (nub < __fmaf_rn(b2v, b2v, -EPS)) done = true;
                }
            }
            MERGE(res0, res1, res2, res3, mb3)
        }
    }
#undef BOXBOUND
#undef MERGE
#undef RUN
#undef PAIR
    if (lane == 0) g_nn[qid] = make_int4(res0, res1, res2, res3);
}

// ---------------------------------------------------------------------------
// K4: gather from channel-contiguous vt rows + mean (8 ch/thread, grid.y=8);
// re-zero histogram counters for the next graph replay.
// ---------------------------------------------------------------------------
__global__ void __launch_bounds__(256) k_gather(float* __restrict__ out)
{
    const int i  = blockIdx.x * 256 + threadIdx.x;
    if (blockIdx.y == 0 && i < NCELL) { g_cnt[i] = 0; g_qcnt[i] = 0; }

    const int c0 = blockIdx.y * 8;
    int4 nn = g_nn[i];
    const float4* v0 = (const float4*)(g_vt + nn.x * CH + c0);
    const float4* v1 = (const float4*)(g_vt + nn.y * CH + c0);
    const float4* v2 = (const float4*)(g_vt + nn.z * CH + c0);
    const float4* v3 = (const float4*)(g_vt + nn.w * CH + c0);
    #pragma unroll
    for (int k = 0; k < 2; k++) {
        float4 a = v0[k], b = v1[k], c = v2[k], d = v3[k];
        int cc = c0 + k * 4;
        out[(cc + 0) * NQ + i] =
            __fmul_rn(__fadd_rn(__fadd_rn(__fadd_rn(a.x, b.x), c.x), d.x), 0.25f);
        out[(cc + 1) * NQ + i] =
            __fmul_rn(__fadd_rn(__fadd_rn(__fadd_rn(a.y, b.y), c.y), d.y), 0.25f);
        out[(cc + 2) * NQ + i] =
            __fmul_rn(__fadd_rn(__fadd_rn(__fadd_rn(a.z, b.z), c.z), d.z), 0.25f);
        out[(cc + 3) * NQ + i] =
            __fmul_rn(__fadd_rn(__fadd_rn(__fadd_rn(a.w, b.w), c.w), d.w), 0.25f);
    }
}

extern "C" void kernel_launch(void* const* d_in, const int* in_sizes, int n_in,
                              void* d_out, int out_size)
{
    const float*  values = (const float*)  d_in[0];  // [64, 8192]
    const float2* coords = (const float2*) d_in[1];  // [8192, 2]
    const float2* newc   = (const float2*) d_in[2];  // [24576, 2]
    const float*  shift  = (const float*)  d_in[3];  // [2]
    float* out = (float*)d_out;                      // [64, 32768]

    k_pre    <<<HB, 256>>>(coords, newc, shift);
    k_scatter<<<HB + T_TILES, 256>>>(values, coords, newc, shift);
    k_query  <<<NQ * L / 256, 256>>>();
    k_gather <<<dim3(NQ / 256, 8), 256>>>(out);
}

// round 8
// speedup vs baseline: 5.3204x; 1.0216x over previous
#include <cuda_runtime.h>

#define NP     8192
#define NQ     32768
#define CH     64
#define G      64
#define NCELL  (G * G)
#define HCELL  (1.0f / 64.0f)   // exact power of two
#define EPS    1e-5f            // pruning margin >> fp formula error (~2e-6)

#define T_TILES 512             // 32x32 transpose tiles: (64/32)*(8192/32)
#define L      8                // lanes cooperating per query
#define HB     (NQ / 256)       // hist blocks in k_pre

// ---- scratch (__device__ globals: allocation-free rule) ----
// Counters start zero (static init) and are re-zeroed by k_out each call.
__device__ int    g_cnt[NCELL],  g_off[NCELL + 1];    // points
__device__ int    g_qcnt[NCELL], g_qoff[NCELL + 1];   // queries
__device__ unsigned g_done;      // k_pre tail-block counter (self-resetting)
__device__ int    g_pkey[NP];    // packed cell<<16 | rank  (points)
__device__ int    g_qkey[NQ];    // packed cell<<16 | rank  (queries)
__device__ float4 g_pts[NP];     // cell-sorted points : (x, y, |c|^2, orig-id)
__device__ float4 g_q[NQ];       // cell-sorted queries: (qx, qy, |q|^2, qid)
__device__ int4   g_nn[NQ];      // per SORTED pos: 4 neighbor ORIG ids
__device__ int    g_qid[NQ];     // per SORTED pos: original query id
__device__ float  g_vt[NP * CH]; // values transposed: vt[orig][c]
__device__ float  g_ot[NQ * CH]; // result staged as ot[qid][c]

static __device__ __forceinline__ int cell_clamped(float px, float py) {
    int cx = (int)(px * (float)G); cx = cx < 0 ? 0 : (cx > G - 1 ? G - 1 : cx);
    int cy = (int)(py * (float)G); cy = cy < 0 ? 0 : (cy > G - 1 ? G - 1 : cy);
    return cy * G + cx;
}

// ---------------------------------------------------------------------------
// K1: histogram-with-rank; LAST block also runs the dual scan
// (threadfence + done-counter tail-block pattern, counter self-resets).
// ---------------------------------------------------------------------------
__global__ void __launch_bounds__(256) k_pre(
    const float2* __restrict__ coords,
    const float2* __restrict__ newc,
    const float*  __restrict__ shift)
{
    int i = blockIdx.x * 256 + threadIdx.x;   // 0..NQ-1
    float sx = shift[0], sy = shift[1];
    float2 a = (i < NP) ? coords[i] : newc[i - NP];
    float qx = __fsub_rn(a.x, sx), qy = __fsub_rn(a.y, sy);
    int qc = cell_clamped(qx, qy);
    int qr = atomicAdd(&g_qcnt[qc], 1);
    g_qkey[i] = (qc << 16) | qr;
    if (i < NP) {
        int pc = cell_clamped(a.x, a.y);
        int pr = atomicAdd(&g_cnt[pc], 1);
        g_pkey[i] = (pc << 16) | pr;
    }

    __threadfence();
    __shared__ bool isLast;
    if (threadIdx.x == 0)
        isLast = (atomicAdd(&g_done, 1u) == HB - 1);
    __syncthreads();
    if (!isLast) return;
    if (threadIdx.x == 0) g_done = 0;          // reset for next replay

    // ---- dual exclusive scan of both 4096-cell histograms ----
    __shared__ int pp[256], pq[256];
    int t = threadIdx.x, base = t * 16;
    int lp[16], lq[16], sp = 0, sq = 0;
    #pragma unroll
    for (int k = 0; k < 16; k++) {
        lp[k] = sp; sp += g_cnt[base + k];
        lq[k] = sq; sq += g_qcnt[base + k];
    }
    pp[t] = sp; pq[t] = sq;
    __syncthreads();
    for (int o = 1; o < 256; o <<= 1) {
        int vp = (t >= o) ? pp[t - o] : 0;
        int vq = (t >= o) ? pq[t - o] : 0;
        __syncthreads();
        pp[t] += vp; pq[t] += vq;
        __syncthreads();
    }
    int prep = (t == 0) ? 0 : pp[t - 1];
    int preq = (t == 0) ? 0 : pq[t - 1];
    #pragma unroll
    for (int k = 0; k < 16; k++) {
        g_off[base + k]  = prep + lp[k];
        g_qoff[base + k] = preq + lq[k];
    }
    if (t == 255) { g_off[NCELL] = NP; g_qoff[NCELL] = NQ; }
}

// ---------------------------------------------------------------------------
// K2: atomic-free scatter (blocks [0,HB)) + values-transpose (rest).
// ---------------------------------------------------------------------------
__global__ void __launch_bounds__(256) k_scatter(
    const float*  __restrict__ values,
    const float2* __restrict__ coords,
    const float2* __restrict__ newc,
    const float*  __restrict__ shift)
{
    if (blockIdx.x >= HB) {
        __shared__ float s[32][33];
        int tb = blockIdx.x - HB;
        int tc = tb & 1;
        int to = tb >> 1;
        int tx = threadIdx.x & 31, ty = threadIdx.x >> 5;
        #pragma unroll
        for (int d = 0; d < 4; d++) {
            int cl = ty + d * 8;
            s[cl][tx] = values[(tc * 32 + cl) * NP + to * 32 + tx];
        }
        __syncthreads();
        #pragma unroll
        for (int d = 0; d < 4; d++) {
            int ol = ty + d * 8;
            g_vt[(to * 32 + ol) * CH + tc * 32 + tx] = s[tx][ol];
        }
        return;
    }
    int i = blockIdx.x * 256 + threadIdx.x;
    float sx = shift[0], sy = shift[1];
    float2 a = (i < NP) ? coords[i] : newc[i - NP];
    float qx = __fsub_rn(a.x, sx), qy = __fsub_rn(a.y, sy);
    float sq = __fadd_rn(__fmul_rn(qx, qx), __fmul_rn(qy, qy));
    int qk = g_qkey[i];
    g_q[g_qoff[qk >> 16] + (qk & 0xffff)] =
        make_float4(qx, qy, sq, __int_as_float(i));
    if (i < NP) {
        int pk = g_pkey[i];
        float c2 = __fadd_rn(__fmul_rn(a.x, a.x), __fmul_rn(a.y, a.y));
        g_pts[g_off[pk >> 16] + (pk & 0xffff)] =
            make_float4(a.x, a.y, c2, __int_as_float(i));
    }
}

// ---------------------------------------------------------------------------
// K3: exact 4-NN, 8 lanes/query, adaptive sweep (3x3 -> ring2 -> safety
// rings). Per-pair fp32 arithmetic identical to the verified brute force;
// (d, orig_id) lexicographic selection exact. Results stored per SORTED
// position (+ qid) for the locality-friendly gather.
// ---------------------------------------------------------------------------
__global__ void __launch_bounds__(256) k_query()
{
    const int gt   = blockIdx.x * 256 + threadIdx.x;
    const int grp  = gt >> 3;          // query index (sorted order)
    const int lane = gt & 7;

    float4 q = g_q[grp];
    const float qx = q.x, qy = q.y, sq = q.z;
    const int qid = __float_as_int(q.w);
    const int cx = (int)floorf(qx * (float)G);   // may be -1 near lower edge
    const int cy = (int)floorf(qy * (float)G);

    const float INF = __int_as_float(0x7f800000);
    float b0 = INF, b1 = INF, b2 = INF, b3 = INF;
    int   o0 = 0x7fffffff, o1 = 0x7fffffff, o2 = 0x7fffffff, o3 = 0x7fffffff;

#define PAIR(n) {                                                        \
    float4 p = g_pts[n];                                                 \
    float qc = __fmaf_rn(qy, p.y, __fmul_rn(qx, p.x));                   \
    float tt = __fadd_rn(sq, p.z);                                       \
    float d  = __fmaf_rn(-2.0f, qc, tt);                                 \
    int  id  = __float_as_int(p.w);                                      \
    if ((d < b3) || (d == b3 && id < o3)) {                              \
        if ((d < b2) || (d == b2 && id < o2)) {                          \
            b3 = b2; o3 = o2;                                            \
            if ((d < b1) || (d == b1 && id < o1)) {                      \
                b2 = b1; o2 = o1;                                        \
                if ((d < b0) || (d == b0 && id < o0)) {                  \
                    b1 = b0; o1 = o0; b0 = d; o0 = id;                   \
                } else { b1 = d; o1 = id; }                              \
            } else { b2 = d; o2 = id; }                                  \
        } else { b3 = d; o3 = id; }                                      \
    } }

#define RUN(s_, e_) { for (int n = (s_) + lane; n < (e_); n += L) PAIR(n) }

#define MERGE(R0, R1, R2, R3, B3V) {                                    \
    int h = 0;                                                          \
    _Pragma("unroll")                                                   \
    for (int k = 0; k < 4; k++) {                                       \
        float cd = (h == 0) ? b0 : (h == 1) ? b1 : (h == 2) ? b2        \
                 : (h == 3) ? b3 : INF;                                 \
        int   ci = (h == 0) ? o0 : (h == 1) ? o1 : (h == 2) ? o2        \
                 : (h == 3) ? o3 : 0x7fffffff;                          \
        float md = cd; int mi = ci;                                     \
        _Pragma("unroll")                                               \
        for (int s = 1; s < L; s <<= 1) {                               \
            float od = __shfl_xor_sync(0xffffffffu, md, s, L);          \
            int   oi = __shfl_xor_sync(0xffffffffu, mi, s, L);          \
            if (od < md || (od == md && oi < mi)) { md = od; mi = oi; } \
        }                                                               \
        if (k == 0) R0 = mi; else if (k == 1) R1 = mi;                  \
        else if (k == 2) R2 = mi; else { R3 = mi; B3V = md; }           \
        if (cd == md && ci == mi) h++;                                  \
    } }

#define BOXBOUND(e_, bv_) {                                              \
    float x0 = (float)(cx - (e_)) * HCELL, y0 = (float)(cy - (e_)) * HCELL; \
    float x1 = (float)(cx + (e_) + 1) * HCELL, y1 = (float)(cy + (e_) + 1) * HCELL; \
    bv_ = fminf(fminf(qx - x0, x1 - qx), fminf(qy - y0, y1 - qy)); }

    // ---- phase 1: 3x3 sweep (row-contiguous) ----
    {
        int iy0 = cy - 1 < 0 ? 0 : cy - 1;
        int iy1 = cy + 1 > G - 1 ? G - 1 : cy + 1;
        int ix0 = cx - 1 < 0 ? 0 : cx - 1;
        int ix1 = cx + 1 > G - 1 ? G - 1 : cx + 1;
        for (int iy = iy0; iy <= iy1; iy++)
            RUN(g_off[iy * G + ix0], g_off[iy * G + ix1 + 1])
    }
    int res0, res1, res2, res3;
    float mb3;
    MERGE(res0, res1, res2, res3, mb3)

    float bb; BOXBOUND(1, bb)
    bool done = (mb3 < __fmaf_rn(bb, bb, -EPS));

    if (!__all_sync(0xffffffffu, done)) {
        // ---- phase 2: ring r=2 (guarded per group; no shfl inside) ----
        if (!done) {
            int ix0 = cx - 2 < 0 ? 0 : cx - 2;
            int ix1 = cx + 2 > G - 1 ? G - 1 : cx + 2;
            if (cy - 2 >= 0)
                RUN(g_off[(cy - 2) * G + ix0], g_off[(cy - 2) * G + ix1 + 1])
            if (cy + 2 <= G - 1)
                RUN(g_off[(cy + 2) * G + ix0], g_off[(cy + 2) * G + ix1 + 1])
            int iy0 = cy - 1 < 0 ? 0 : cy - 1;
            int iy1 = cy + 1 > G - 1 ? G - 1 : cy + 1;
            for (int iy = iy0; iy <= iy1; iy++) {
                if (cx - 2 >= 0) {
                    int c = iy * G + cx - 2;
                    RUN(g_off[c], g_off[c + 1])
                }
                if (cx + 2 <= G - 1) {
                    int c = iy * G + cx + 2;
                    RUN(g_off[c], g_off[c + 1])
                }
            }
        }
        MERGE(res0, res1, res2, res3, mb3)   // uniform re-merge (safe for done)
        BOXBOUND(2, bb)
        done = done || (mb3 < __fmaf_rn(bb, bb, -EPS));

        if (!__all_sync(0xffffffffu, done)) {
            // ---- phase 3: safety rings r>=3 ----
            for (int r = 3; r < 96; r++) {
                if (__all_sync(0xffffffffu, done)) break;
                if (!done) {
                    int ylo = cy - r, yhi = cy + r, xlo = cx - r, xhi = cx + r;
                    int ix0 = xlo < 0 ? 0 : xlo;
                    int ix1 = xhi > G - 1 ? G - 1 : xhi;
                    if (ylo >= 0)
                        RUN(g_off[ylo * G + ix0], g_off[ylo * G + ix1 + 1])
                    if (yhi <= G - 1)
                        RUN(g_off[yhi * G + ix0], g_off[yhi * G + ix1 + 1])
                    int iy0 = ylo + 1 < 0 ? 0 : ylo + 1;
                    int iy1 = yhi - 1 > G - 1 ? G - 1 : yhi - 1;
                    for (int iy = iy0; iy <= iy1; iy++) {
                        if (xlo >= 0) {
                            int c = iy * G + xlo;
                            RUN(g_off[c], g_off[c + 1])
                        }
                        if (xhi <= G - 1) {
                            int c = iy * G + xhi;
                            RUN(g_off[c], g_off[c + 1])
                        }
                    }
                }
                float nub = b3;   // conservative: min over lanes of lane b3
                nub = fminf(nub, __shfl_xor_sync(0xffffffffu, nub, 1, L));
                nub = fminf(nub, __shfl_xor_sync(0xffffffffu, nub, 2, L));
                nub = fminf(nub, __shfl_xor_sync(0xffffffffu, nub, 4, L));
                if (!done) {
                    float b2v; BOXBOUND(r, b2v)
                    if (nub < __fmaf_rn(b2v, b2v, -EPS)) done = true;
                }
            }
            MERGE(res0, res1, res2, res3, mb3)
        }
    }
#undef BOXBOUND
#undef MERGE
#undef RUN
#undef PAIR
    if (lane == 0) {
        g_nn[grp]  = make_int4(res0, res1, res2, res3);
        g_qid[grp] = qid;
    }
}

// ---------------------------------------------------------------------------
// K4: warp-per-SORTED-query gather. Each lane reads float2 from each of the
// 4 neighbor rows (fully coalesced 256B row reads; adjacent sorted queries
// share neighbors -> L1-resident). Result row staged to g_ot[qid][.] (256B
// coalesced store).
// ---------------------------------------------------------------------------
__global__ void __launch_bounds__(256) k_gather()
{
    const int w    = blockIdx.x * 8 + (threadIdx.x >> 5);  // sorted query pos
    const int lane = threadIdx.x & 31;
    int4 nn  = g_nn[w];
    int  qid = g_qid[w];
    const float2* r0 = (const float2*)(g_vt + nn.x * CH);
    const float2* r1 = (const float2*)(g_vt + nn.y * CH);
    const float2* r2 = (const float2*)(g_vt + nn.z * CH);
    const float2* r3 = (const float2*)(g_vt + nn.w * CH);
    float2 a = r0[lane], b = r1[lane], c = r2[lane], d = r3[lane];
    float2 res;
    res.x = __fmul_rn(__fadd_rn(__fadd_rn(__fadd_rn(a.x, b.x), c.x), d.x), 0.25f);
    res.y = __fmul_rn(__fadd_rn(__fadd_rn(__fadd_rn(a.y, b.y), c.y), d.y), 0.25f);
    ((float2*)(g_ot + qid * CH))[lane] = res;
}

// ---------------------------------------------------------------------------
// K5: tiled transpose g_ot[q][c] -> out[c][q] (coalesced both sides);
// re-zeroes histogram counters for the next graph replay.
// ---------------------------------------------------------------------------
__global__ void __launch_bounds__(256) k_out(float* __restrict__ out)
{
    if (blockIdx.y == 0 && blockIdx.x < 16) {
        int z = blockIdx.x * 256 + threadIdx.x;
        g_cnt[z] = 0; g_qcnt[z] = 0;
    }
    __shared__ float s[32][33];
    int q0 = blockIdx.x * 32, c0 = blockIdx.y * 32;
    int tx = threadIdx.x & 31, ty = threadIdx.x >> 5;   // 32 x 8
    #pragma unroll
    for (int d = 0; d < 4; d++)
        s[ty + d * 8][tx] = g_ot[(q0 + ty + d * 8) * CH + c0 + tx];
    __syncthreads();
    #pragma unroll
    for (int d = 0; d < 4; d++)
        out[(c0 + ty + d * 8) * NQ + q0 + tx] = s[tx][ty + d * 8];
}

extern "C" void kernel_launch(void* const* d_in, const int* in_sizes, int n_in,
                              void* d_out, int out_size)
{
    const float*  values = (const float*)  d_in[0];  // [64, 8192]
    const float2* coords = (const float2*) d_in[1];  // [8192, 2]
    const float2* newc   = (const float2*) d_in[2];  // [24576, 2]
    const float*  shift  = (const float*)  d_in[3];  // [2]
    float* out = (float*)d_out;                      // [64, 32768]

    k_pre    <<<HB, 256>>>(coords, newc, shift);
    k_scatter<<<HB + T_TILES, 256>>>(values, coords, newc, shift);
    k_query  <<<NQ * L / 256, 256>>>();
    k_gather <<<NQ / 8, 256>>>();
    k_out    <<<dim3(NQ / 32, CH / 32), 256>>>(out);
}

// round 9
// speedup vs baseline: 6.0132x; 1.1302x over previous
#include <cuda_runtime.h>

#define NP     8192
#define NQ     32768
#define CH     64
#define G      64
#define NCELL  (G * G)
#define HCELL  (1.0f / 64.0f)   // exact power of two
#define EPS    1e-5f            // pruning margin >> fp formula error (~2e-6)

#define T_TILES 512             // 32x32 transpose tiles: (64/32)*(8192/32)
#define L      8                // lanes cooperating per query
#define HB     (NQ / 256)       // hist blocks in k_pre

// ---- scratch (__device__ globals: allocation-free rule) ----
// Counters start zero (static init) and are re-zeroed by k_gather each call.
__device__ int    g_cnt[NCELL],  g_off[NCELL + 1];    // points
__device__ int    g_qcnt[NCELL], g_qoff[NCELL + 1];   // queries
__device__ unsigned g_done;      // k_pre tail-block counter (self-resetting)
__device__ int    g_pkey[NP];    // packed cell<<16 | rank  (points)
__device__ int    g_qkey[NQ];    // packed cell<<16 | rank  (queries)
__device__ float4 g_pts[NP];     // cell-sorted points : (x, y, |c|^2, orig-id)
__device__ float4 g_q[NQ];       // cell-sorted queries: (qx, qy, |q|^2, qid)
__device__ int4   g_nn[NQ];      // per ORIGINAL qid: 4 neighbor ORIG ids
__device__ float  g_vt[NP * CH]; // values transposed: vt[orig][c]

static __device__ __forceinline__ int cell_clamped(float px, float py) {
    int cx = (int)(px * (float)G); cx = cx < 0 ? 0 : (cx > G - 1 ? G - 1 : cx);
    int cy = (int)(py * (float)G); cy = cy < 0 ? 0 : (cy > G - 1 ? G - 1 : cy);
    return cy * G + cx;
}

// ---------------------------------------------------------------------------
// K1: histogram-with-rank; LAST block also runs the dual scan
// (threadfence + done-counter tail-block pattern, counter self-resets).
// ---------------------------------------------------------------------------
__global__ void __launch_bounds__(256) k_pre(
    const float2* __restrict__ coords,
    const float2* __restrict__ newc,
    const float*  __restrict__ shift)
{
    int i = blockIdx.x * 256 + threadIdx.x;   // 0..NQ-1
    float sx = shift[0], sy = shift[1];
    float2 a = (i < NP) ? coords[i] : newc[i - NP];
    float qx = __fsub_rn(a.x, sx), qy = __fsub_rn(a.y, sy);
    int qc = cell_clamped(qx, qy);
    int qr = atomicAdd(&g_qcnt[qc], 1);
    g_qkey[i] = (qc << 16) | qr;
    if (i < NP) {
        int pc = cell_clamped(a.x, a.y);
        int pr = atomicAdd(&g_cnt[pc], 1);
        g_pkey[i] = (pc << 16) | pr;
    }

    __threadfence();
    __shared__ bool isLast;
    if (threadIdx.x == 0)
        isLast = (atomicAdd(&g_done, 1u) == HB - 1);
    __syncthreads();
    if (!isLast) return;
    if (threadIdx.x == 0) g_done = 0;          // reset for next replay

    // ---- dual exclusive scan of both 4096-cell histograms ----
    __shared__ int pp[256], pq[256];
    int t = threadIdx.x, base = t * 16;
    int lp[16], lq[16], sp = 0, sq = 0;
    #pragma unroll
    for (int k = 0; k < 16; k++) {
        lp[k] = sp; sp += g_cnt[base + k];
        lq[k] = sq; sq += g_qcnt[base + k];
    }
    pp[t] = sp; pq[t] = sq;
    __syncthreads();
    for (int o = 1; o < 256; o <<= 1) {
        int vp = (t >= o) ? pp[t - o] : 0;
        int vq = (t >= o) ? pq[t - o] : 0;
        __syncthreads();
        pp[t] += vp; pq[t] += vq;
        __syncthreads();
    }
    int prep = (t == 0) ? 0 : pp[t - 1];
    int preq = (t == 0) ? 0 : pq[t - 1];
    #pragma unroll
    for (int k = 0; k < 16; k++) {
        g_off[base + k]  = prep + lp[k];
        g_qoff[base + k] = preq + lq[k];
    }
    if (t == 255) { g_off[NCELL] = NP; g_qoff[NCELL] = NQ; }
}

// ---------------------------------------------------------------------------
// K2: atomic-free scatter (blocks [0,HB)) + values-transpose (rest).
// ---------------------------------------------------------------------------
__global__ void __launch_bounds__(256) k_scatter(
    const float*  __restrict__ values,
    const float2* __restrict__ coords,
    const float2* __restrict__ newc,
    const float*  __restrict__ shift)
{
    if (blockIdx.x >= HB) {
        __shared__ float s[32][33];
        int tb = blockIdx.x - HB;
        int tc = tb & 1;
        int to = tb >> 1;
        int tx = threadIdx.x & 31, ty = threadIdx.x >> 5;
        #pragma unroll
        for (int d = 0; d < 4; d++) {
            int cl = ty + d * 8;
            s[cl][tx] = values[(tc * 32 + cl) * NP + to * 32 + tx];
        }
        __syncthreads();
        #pragma unroll
        for (int d = 0; d < 4; d++) {
            int ol = ty + d * 8;
            g_vt[(to * 32 + ol) * CH + tc * 32 + tx] = s[tx][ol];
        }
        return;
    }
    int i = blockIdx.x * 256 + threadIdx.x;
    float sx = shift[0], sy = shift[1];
    float2 a = (i < NP) ? coords[i] : newc[i - NP];
    float qx = __fsub_rn(a.x, sx), qy = __fsub_rn(a.y, sy);
    float sq = __fadd_rn(__fmul_rn(qx, qx), __fmul_rn(qy, qy));
    int qk = g_qkey[i];
    g_q[g_qoff[qk >> 16] + (qk & 0xffff)] =
        make_float4(qx, qy, sq, __int_as_float(i));
    if (i < NP) {
        int pk = g_pkey[i];
        float c2 = __fadd_rn(__fmul_rn(a.x, a.x), __fmul_rn(a.y, a.y));
        g_pts[g_off[pk >> 16] + (pk & 0xffff)] =
            make_float4(a.x, a.y, c2, __int_as_float(i));
    }
}

// ---------------------------------------------------------------------------
// K3: exact 4-NN, 8 lanes/query, adaptive sweep (3x3 -> ring2 -> safety
// rings). Per-pair fp32 arithmetic identical to the verified brute force;
// (d, orig_id) lexicographic selection exact. Result -> g_nn[qid].
// ---------------------------------------------------------------------------
__global__ void __launch_bounds__(256) k_query()
{
    const int gt   = blockIdx.x * 256 + threadIdx.x;
    const int grp  = gt >> 3;          // query index (sorted order)
    const int lane = gt & 7;

    float4 q = g_q[grp];
    const float qx = q.x, qy = q.y, sq = q.z;
    const int qid = __float_as_int(q.w);
    const int cx = (int)floorf(qx * (float)G);   // may be -1 near lower edge
    const int cy = (int)floorf(qy * (float)G);

    const float INF = __int_as_float(0x7f800000);
    float b0 = INF, b1 = INF, b2 = INF, b3 = INF;
    int   o0 = 0x7fffffff, o1 = 0x7fffffff, o2 = 0x7fffffff, o3 = 0x7fffffff;

#define PAIR(n) {                                                        \
    float4 p = g_pts[n];                                                 \
    float qc = __fmaf_rn(qy, p.y, __fmul_rn(qx, p.x));                   \
    float tt = __fadd_rn(sq, p.z);                                       \
    float d  = __fmaf_rn(-2.0f, qc, tt);                                 \
    int  id  = __float_as_int(p.w);                                      \
    if ((d < b3) || (d == b3 && id < o3)) {                              \
        if ((d < b2) || (d == b2 && id < o2)) {                          \
            b3 = b2; o3 = o2;                                            \
            if ((d < b1) || (d == b1 && id < o1)) {                      \
                b2 = b1; o2 = o1;                                        \
                if ((d < b0) || (d == b0 && id < o0)) {                  \
                    b1 = b0; o1 = o0; b0 = d; o0 = id;                   \
                } else { b1 = d; o1 = id; }                              \
            } else { b2 = d; o2 = id; }                                  \
        } else { b3 = d; o3 = id; }                                      \
    } }

#define RUN(s_, e_) { for (int n = (s_) + lane; n < (e_); n += L) PAIR(n) }

#define MERGE(R0, R1, R2, R3, B3V) {                                    \
    int h = 0;                                                          \
    _Pragma("unroll")                                                   \
    for (int k = 0; k < 4; k++) {                                       \
        float cd = (h == 0) ? b0 : (h == 1) ? b1 : (h == 2) ? b2        \
                 : (h == 3) ? b3 : INF;                                 \
        int   ci = (h == 0) ? o0 : (h == 1) ? o1 : (h == 2) ? o2        \
                 : (h == 3) ? o3 : 0x7fffffff;                          \
        float md = cd; int mi = ci;                                     \
        _Pragma("unroll")                                               \
        for (int s = 1; s < L; s <<= 1) {                               \
            float od = __shfl_xor_sync(0xffffffffu, md, s, L);          \
            int   oi = __shfl_xor_sync(0xffffffffu, mi, s, L);          \
            if (od < md || (od == md && oi < mi)) { md = od; mi = oi; } \
        }                                                               \
        if (k == 0) R0 = mi; else if (k == 1) R1 = mi;                  \
        else if (k == 2) R2 = mi; else { R3 = mi; B3V = md; }           \
        if (cd == md && ci == mi) h++;                                  \
    } }

#define BOXBOUND(e_, bv_) {                                              \
    float x0 = (float)(cx - (e_)) * HCELL, y0 = (float)(cy - (e_)) * HCELL; \
    float x1 = (float)(cx + (e_) + 1) * HCELL, y1 = (float)(cy + (e_) + 1) * HCELL; \
    bv_ = fminf(fminf(qx - x0, x1 - qx), fminf(qy - y0, y1 - qy)); }

    // ---- phase 1: 3x3 sweep (row-contiguous) ----
    {
        int iy0 = cy - 1 < 0 ? 0 : cy - 1;
        int iy1 = cy + 1 > G - 1 ? G - 1 : cy + 1;
        int ix0 = cx - 1 < 0 ? 0 : cx - 1;
        int ix1 = cx + 1 > G - 1 ? G - 1 : cx + 1;
        for (int iy = iy0; iy <= iy1; iy++)
            RUN(g_off[iy * G + ix0], g_off[iy * G + ix1 + 1])
    }
    int res0, res1, res2, res3;
    float mb3;
    MERGE(res0, res1, res2, res3, mb3)

    float bb; BOXBOUND(1, bb)
    bool done = (mb3 < __fmaf_rn(bb, bb, -EPS));

    if (!__all_sync(0xffffffffu, done)) {
        // ---- phase 2: ring r=2 (guarded per group; no shfl inside) ----
        if (!done) {
            int ix0 = cx - 2 < 0 ? 0 : cx - 2;
            int ix1 = cx + 2 > G - 1 ? G - 1 : cx + 2;
            if (cy - 2 >= 0)
                RUN(g_off[(cy - 2) * G + ix0], g_off[(cy - 2) * G + ix1 + 1])
            if (cy + 2 <= G - 1)
                RUN(g_off[(cy + 2) * G + ix0], g_off[(cy + 2) * G + ix1 + 1])
            int iy0 = cy - 1 < 0 ? 0 : cy - 1;
            int iy1 = cy + 1 > G - 1 ? G - 1 : cy + 1;
            for (int iy = iy0; iy <= iy1; iy++) {
                if (cx - 2 >= 0) {
                    int c = iy * G + cx - 2;
                    RUN(g_off[c], g_off[c + 1])
                }
                if (cx + 2 <= G - 1) {
                    int c = iy * G + cx + 2;
                    RUN(g_off[c], g_off[c + 1])
                }
            }
        }
        MERGE(res0, res1, res2, res3, mb3)   // uniform re-merge (safe for done)
        BOXBOUND(2, bb)
        done = done || (mb3 < __fmaf_rn(bb, bb, -EPS));

        if (!__all_sync(0xffffffffu, done)) {
            // ---- phase 3: safety rings r>=3 ----
            for (int r = 3; r < 96; r++) {
                if (__all_sync(0xffffffffu, done)) break;
                if (!done) {
                    int ylo = cy - r, yhi = cy + r, xlo = cx - r, xhi = cx + r;
                    int ix0 = xlo < 0 ? 0 : xlo;
                    int ix1 = xhi > G - 1 ? G - 1 : xhi;
                    if (ylo >= 0)
                        RUN(g_off[ylo * G + ix0], g_off[ylo * G + ix1 + 1])
                    if (yhi <= G - 1)
                        RUN(g_off[yhi * G + ix0], g_off[yhi * G + ix1 + 1])
                    int iy0 = ylo + 1 < 0 ? 0 : ylo + 1;
                    int iy1 = yhi - 1 > G - 1 ? G - 1 : yhi - 1;
                    for (int iy = iy0; iy <= iy1; iy++) {
                        if (xlo >= 0) {
                            int c = iy * G + xlo;
                            RUN(g_off[c], g_off[c + 1])
                        }
                        if (xhi <= G - 1) {
                            int c = iy * G + xhi;
                            RUN(g_off[c], g_off[c + 1])
                        }
                    }
                }
                float nub = b3;   // conservative: min over lanes of lane b3
                nub = fminf(nub, __shfl_xor_sync(0xffffffffu, nub, 1, L));
                nub = fminf(nub, __shfl_xor_sync(0xffffffffu, nub, 2, L));
                nub = fminf(nub, __shfl_xor_sync(0xffffffffu, nub, 4, L));
                if (!done) {
                    float b2v; BOXBOUND(r, b2v)
                    if (nub < __fmaf_rn(b2v, b2v, -EPS)) done = true;
                }
            }
            MERGE(res0, res1, res2, res3, mb3)
        }
    }
#undef BOXBOUND
#undef MERGE
#undef RUN
#undef PAIR
    if (lane == 0) g_nn[qid] = make_int4(res0, res1, res2, res3);
}

// ---------------------------------------------------------------------------
// K4: FUSED gather + transpose, qid-major. Block = 64 consecutive qids,
// warp = 8 qids; each lane reads float2 from 32 neighbor rows (huge MLP,
// rows 256B-coalesced, g_vt is L2-resident). Sums staged in a 64x64 smem
// tile (pad 65 -> conflict-free transposed reads), then written to
// out[c][q0..q0+63] as coalesced rows. Also re-zeroes the histogram
// counters for the next graph replay.
// ---------------------------------------------------------------------------
__global__ void __launch_bounds__(256) k_gather(float* __restrict__ out)
{
    __shared__ float s[64 * 65];

    if (blockIdx.x < 16) {
        int z = blockIdx.x * 256 + threadIdx.x;
        g_cnt[z] = 0; g_qcnt[z] = 0;
    }

    const int q0   = blockIdx.x * 64;
    const int wid  = threadIdx.x >> 5;       // 0..7
    const int lane = threadIdx.x & 31;

    #pragma unroll
    for (int k = 0; k < 8; k++) {
        int ql  = wid * 8 + k;                // 0..63 within tile
        int4 nn = g_nn[q0 + ql];              // broadcast load (same addr/warp)
        const float2* r0 = (const float2*)(g_vt + nn.x * CH);
        const float2* r1 = (const float2*)(g_vt + nn.y * CH);
        const float2* r2 = (const float2*)(g_vt + nn.z * CH);
        const float2* r3 = (const float2*)(g_vt + nn.w * CH);
        float2 a = r0[lane], b = r1[lane], c = r2[lane], d = r3[lane];
        float rx = __fmul_rn(__fadd_rn(__fadd_rn(__fadd_rn(a.x, b.x), c.x), d.x), 0.25f);
        float ry = __fmul_rn(__fadd_rn(__fadd_rn(__fadd_rn(a.y, b.y), c.y), d.y), 0.25f);
        s[ql * 65 + 2 * lane]     = rx;
        s[ql * 65 + 2 * lane + 1] = ry;
    }
    __syncthreads();

    // transposed write: 256 threads cover the 64x64 tile in 16 passes
    const int tq = threadIdx.x & 63;          // query within tile
    const int tc0 = threadIdx.x >> 6;         // 0..3
    #pragma unroll
    for (int cc = 0; cc < 16; cc++) {
        int c = tc0 + cc * 4;
        out[c * NQ + q0 + tq] = s[tq * 65 + c];
    }
}

extern "C" void kernel_launch(void* const* d_in, const int* in_sizes, int n_in,
                              void* d_out, int out_size)
{
    const float*  values = (const float*)  d_in[0];  // [64, 8192]
    const float2* coords = (const float2*) d_in[1];  // [8192, 2]
    const float2* newc   = (const float2*) d_in[2];  // [24576, 2]
    const float*  shift  = (const float*)  d_in[3];  // [2]
    float* out = (float*)d_out;                      // [64, 32768]

    k_pre    <<<HB, 256>>>(coords, newc, shift);
    k_scatter<<<HB + T_TILES, 256>>>(values, coords, newc, shift);
    k_query  <<<NQ * L / 256, 256>>>();
    k_gather <<<NQ / 64, 256>>>(out);
}